// round 1
// baseline (speedup 1.0000x reference)
#include <cuda_runtime.h>
#include <cstdint>
#include <cstddef>

// Problem dims (fixed by the reference)
#define BATCH 4096
#define DIM   1024   // all layer dims are 1024

// ---------------- scratch (static device memory; no runtime allocation) ----
__device__ float g_wm[6u * 1024u * 1024u];   // tf32-rounded masked weights: s1,s2,s3,t1,t2,t3
__device__ float g_x32[BATCH * DIM];         // tf32-rounded input copy
__device__ float g_h1[BATCH * DIM];
__device__ float g_h2[BATCH * DIM];
__device__ float g_m [BATCH * DIM];
__device__ float g_a [BATCH * DIM];

// ---------------- helpers ---------------------------------------------------
__device__ __forceinline__ float tf32_rna(float x) {
    uint32_t u;
    asm("cvt.rna.tf32.f32 %0, %1;" : "=r"(u) : "f"(x));
    return __uint_as_float(u);
}

__device__ __forceinline__ void mma_tf32(float& d0, float& d1, float& d2, float& d3,
                                         uint32_t a0, uint32_t a1, uint32_t a2, uint32_t a3,
                                         uint32_t b0, uint32_t b1) {
    asm("mma.sync.aligned.m16n8k8.row.col.f32.tf32.tf32.f32 "
        "{%0,%1,%2,%3},{%4,%5,%6,%7},{%8,%9},{%0,%1,%2,%3};\n"
        : "+f"(d0), "+f"(d1), "+f"(d2), "+f"(d3)
        : "r"(a0), "r"(a1), "r"(a2), "r"(a3), "r"(b0), "r"(b1));
}

// ---------------- prep kernels ----------------------------------------------
// wm = tf32_round(w * mask); processes float4 per thread.
__global__ void prep_weight_kernel(const float* __restrict__ w,
                                   const float* __restrict__ msk,
                                   float* __restrict__ dst) {
    int i = blockIdx.x * blockDim.x + threadIdx.x;       // over 1M/4 = 262144 float4
    float4 wv = reinterpret_cast<const float4*>(w)[i];
    float4 mv = reinterpret_cast<const float4*>(msk)[i];
    float4 o;
    o.x = tf32_rna(wv.x * mv.x);
    o.y = tf32_rna(wv.y * mv.y);
    o.z = tf32_rna(wv.z * mv.z);
    o.w = tf32_rna(wv.w * mv.w);
    reinterpret_cast<float4*>(dst)[i] = o;
}

__global__ void prep_x_kernel(const float* __restrict__ x, float* __restrict__ dst) {
    int i = blockIdx.x * blockDim.x + threadIdx.x;       // over 4M/4 = 1048576 float4
    float4 v = reinterpret_cast<const float4*>(x)[i];
    float4 o;
    o.x = tf32_rna(v.x);
    o.y = tf32_rna(v.y);
    o.z = tf32_rna(v.z);
    o.w = tf32_rna(v.w);
    reinterpret_cast<float4*>(dst)[i] = o;
}

// ---------------- GEMM: C = act(A @ W^T + bias) -----------------------------
// A: [4096, 1024] row-major (tf32-rounded fp32), W: [1024(out), 1024(in)] row-major.
// Tile: BM=128, BN=128, BK=32. 256 threads = 8 warps (2 x 4), warp tile 64x32.
#define ACT_TANH 0
#define ACT_RELU 1
#define ACT_NONE 2

#define GBM 128
#define GBN 128
#define GBK 32
#define SPAD 36   // smem row stride in floats (conflict-free fragment gathers)

template <int ACT>
__global__ __launch_bounds__(256, 2)
void gemm_act_kernel(const float* __restrict__ A, const float* __restrict__ W,
                     const float* __restrict__ bias, float* __restrict__ C) {
    __shared__ __align__(16) float As[GBM * SPAD];
    __shared__ __align__(16) float Bs[GBN * SPAD];

    const int tid   = threadIdx.x;
    const int warp  = tid >> 5;
    const int lane  = tid & 31;
    const int warpM = warp >> 2;          // 0..1  -> 64 rows each
    const int warpN = warp & 3;           // 0..3  -> 32 cols each
    const int qr    = lane >> 2;          // 0..7
    const int qc    = lane & 3;           // 0..3

    const int rowA0 = blockIdx.y * GBM;   // batch rows
    const int colB0 = blockIdx.x * GBN;   // output features

    float acc[4][4][4];
#pragma unroll
    for (int mf = 0; mf < 4; ++mf)
#pragma unroll
        for (int nf = 0; nf < 4; ++nf)
#pragma unroll
            for (int r = 0; r < 4; ++r) acc[mf][nf][r] = 0.f;

    for (int kt = 0; kt < DIM / GBK; ++kt) {
        // ---- load tiles (A: 128x32, Bs holds W rows as [n][k]) ----
#pragma unroll
        for (int i = 0; i < 4; ++i) {
            int idx = tid + i * 256;           // 0..1023
            int r   = idx >> 3;                // 0..127
            int c4  = idx & 7;                 // 0..7 (float4 within row)
            float4 va = *reinterpret_cast<const float4*>(
                A + (size_t)(rowA0 + r) * DIM + kt * GBK + c4 * 4);
            *reinterpret_cast<float4*>(&As[r * SPAD + c4 * 4]) = va;
            float4 vb = *reinterpret_cast<const float4*>(
                W + (size_t)(colB0 + r) * DIM + kt * GBK + c4 * 4);
            *reinterpret_cast<float4*>(&Bs[r * SPAD + c4 * 4]) = vb;
        }
        __syncthreads();

        // ---- compute 4 k-steps of 8 ----
#pragma unroll
        for (int kk = 0; kk < GBK; kk += 8) {
            uint32_t afr[4][4];
            uint32_t bfr[4][2];
#pragma unroll
            for (int mf = 0; mf < 4; ++mf) {
                int row0 = warpM * 64 + mf * 16 + qr;
                afr[mf][0] = __float_as_uint(As[(row0    ) * SPAD + kk + qc    ]);
                afr[mf][1] = __float_as_uint(As[(row0 + 8) * SPAD + kk + qc    ]);
                afr[mf][2] = __float_as_uint(As[(row0    ) * SPAD + kk + qc + 4]);
                afr[mf][3] = __float_as_uint(As[(row0 + 8) * SPAD + kk + qc + 4]);
            }
#pragma unroll
            for (int nf = 0; nf < 4; ++nf) {
                int n0 = warpN * 32 + nf * 8 + qr;
                bfr[nf][0] = __float_as_uint(Bs[n0 * SPAD + kk + qc    ]);
                bfr[nf][1] = __float_as_uint(Bs[n0 * SPAD + kk + qc + 4]);
            }
#pragma unroll
            for (int mf = 0; mf < 4; ++mf)
#pragma unroll
                for (int nf = 0; nf < 4; ++nf)
                    mma_tf32(acc[mf][nf][0], acc[mf][nf][1], acc[mf][nf][2], acc[mf][nf][3],
                             afr[mf][0], afr[mf][1], afr[mf][2], afr[mf][3],
                             bfr[nf][0], bfr[nf][1]);
        }
        __syncthreads();
    }

    // ---- epilogue: bias + activation (+ tf32 requantize for intermediates) ----
#pragma unroll
    for (int mf = 0; mf < 4; ++mf) {
#pragma unroll
        for (int nf = 0; nf < 4; ++nf) {
            int row0 = rowA0 + warpM * 64 + mf * 16 + qr;
            int col0 = colB0 + warpN * 32 + nf * 8 + 2 * qc;
            float b0 = bias[col0];
            float b1 = bias[col0 + 1];
            float v0 = acc[mf][nf][0] + b0;
            float v1 = acc[mf][nf][1] + b1;
            float v2 = acc[mf][nf][2] + b0;
            float v3 = acc[mf][nf][3] + b1;
            if (ACT == ACT_TANH) {
                v0 = tf32_rna(tanhf(v0)); v1 = tf32_rna(tanhf(v1));
                v2 = tf32_rna(tanhf(v2)); v3 = tf32_rna(tanhf(v3));
            } else if (ACT == ACT_RELU) {
                v0 = tf32_rna(fmaxf(v0, 0.f)); v1 = tf32_rna(fmaxf(v1, 0.f));
                v2 = tf32_rna(fmaxf(v2, 0.f)); v3 = tf32_rna(fmaxf(v3, 0.f));
            }
            *reinterpret_cast<float2*>(C + (size_t)row0 * DIM + col0)       = make_float2(v0, v1);
            *reinterpret_cast<float2*>(C + (size_t)(row0 + 8) * DIM + col0) = make_float2(v2, v3);
        }
    }
}

// ---------------- final elementwise + logdet reduction ----------------------
__global__ void final_kernel(const float* __restrict__ x, const float* __restrict__ m,
                             const float* __restrict__ a, float* __restrict__ out) {
    int b = blockIdx.x;
    int t = threadIdx.x;
    size_t base = (size_t)b * DIM;
    float s = 0.f;
#pragma unroll
    for (int i = 0; i < 4; ++i) {
        int c = t + i * 256;
        float av = a[base + c];
        float mv = m[base + c];
        float xv = x[base + c];
        out[base + c] = (xv - mv) * expf(-av);
        s += av;
    }
    // block reduction of s
#pragma unroll
    for (int o = 16; o; o >>= 1) s += __shfl_down_sync(0xFFFFFFFFu, s, o);
    __shared__ float ws[8];
    if ((t & 31) == 0) ws[t >> 5] = s;
    __syncthreads();
    if (t < 8) {
        float v = ws[t];
#pragma unroll
        for (int o = 4; o; o >>= 1) v += __shfl_down_sync(0xFFu, v, o);
        if (t == 0) out[(size_t)BATCH * DIM + b] = -v;
    }
}

// ---------------- launcher ---------------------------------------------------
extern "C" void kernel_launch(void* const* d_in, const int* in_sizes, int n_in,
                              void* d_out, int out_size) {
    (void)in_sizes; (void)n_in; (void)out_size;
    // Input order (metadata): inputs, s_w1,s_b1,s_w2,s_b2,s_w3,s_b3,
    //                         t_w1,t_b1,t_w2,t_b2,t_w3,t_b3, mask_in,mask_hid,mask_out
    const float* x      = (const float*)d_in[0];
    const float* s_w1   = (const float*)d_in[1];
    const float* s_b1   = (const float*)d_in[2];
    const float* s_w2   = (const float*)d_in[3];
    const float* s_b2   = (const float*)d_in[4];
    const float* s_w3   = (const float*)d_in[5];
    const float* s_b3   = (const float*)d_in[6];
    const float* t_w1   = (const float*)d_in[7];
    const float* t_b1   = (const float*)d_in[8];
    const float* t_w2   = (const float*)d_in[9];
    const float* t_b2   = (const float*)d_in[10];
    const float* t_w3   = (const float*)d_in[11];
    const float* t_b3   = (const float*)d_in[12];
    const float* mask_in  = (const float*)d_in[13];
    const float* mask_hid = (const float*)d_in[14];
    const float* mask_out = (const float*)d_in[15];
    float* out = (float*)d_out;

    float *wm, *x32, *h1, *h2, *mbuf, *abuf;
    cudaGetSymbolAddress((void**)&wm,   g_wm);
    cudaGetSymbolAddress((void**)&x32,  g_x32);
    cudaGetSymbolAddress((void**)&h1,   g_h1);
    cudaGetSymbolAddress((void**)&h2,   g_h2);
    cudaGetSymbolAddress((void**)&mbuf, g_m);
    cudaGetSymbolAddress((void**)&abuf, g_a);

    const size_t WSZ = 1024u * 1024u;
    float* wm_s1 = wm + 0 * WSZ;
    float* wm_s2 = wm + 1 * WSZ;
    float* wm_s3 = wm + 2 * WSZ;
    float* wm_t1 = wm + 3 * WSZ;
    float* wm_t2 = wm + 4 * WSZ;
    float* wm_t3 = wm + 5 * WSZ;

    // prep: masked weights (tf32-rounded) + rounded input copy
    prep_weight_kernel<<<1024, 256>>>(s_w1, mask_in,  wm_s1);
    prep_weight_kernel<<<1024, 256>>>(s_w2, mask_hid, wm_s2);
    prep_weight_kernel<<<1024, 256>>>(s_w3, mask_out, wm_s3);
    prep_weight_kernel<<<1024, 256>>>(t_w1, mask_in,  wm_t1);
    prep_weight_kernel<<<1024, 256>>>(t_w2, mask_hid, wm_t2);
    prep_weight_kernel<<<1024, 256>>>(t_w3, mask_out, wm_t3);
    prep_x_kernel<<<4096, 256>>>(x, x32);

    dim3 grid(DIM / GBN, BATCH / GBM);   // (8, 32)
    // s branch (tanh)
    gemm_act_kernel<ACT_TANH><<<grid, 256>>>(x32, wm_s1, s_b1, h1);
    gemm_act_kernel<ACT_TANH><<<grid, 256>>>(h1,  wm_s2, s_b2, h2);
    gemm_act_kernel<ACT_NONE><<<grid, 256>>>(h2,  wm_s3, s_b3, mbuf);
    // t branch (relu)
    gemm_act_kernel<ACT_RELU><<<grid, 256>>>(x32, wm_t1, t_b1, h1);
    gemm_act_kernel<ACT_RELU><<<grid, 256>>>(h1,  wm_t2, t_b2, h2);
    gemm_act_kernel<ACT_NONE><<<grid, 256>>>(h2,  wm_t3, t_b3, abuf);

    final_kernel<<<BATCH, 256>>>(x, mbuf, abuf, out);
}

// round 3
// speedup vs baseline: 1.0706x; 1.0706x over previous
#include <cuda_runtime.h>
#include <cstdint>
#include <cstddef>

#define BATCH 4096
#define DIM   1024

// ---------------- scratch (static device memory) ----------------------------
__device__ float g_wm[6u * 1024u * 1024u];   // tf32-rounded masked weights
__device__ float g_x32[BATCH * DIM];
__device__ float g_h1[BATCH * DIM];
__device__ float g_h2[BATCH * DIM];
__device__ float g_m [BATCH * DIM];
__device__ float g_a [BATCH * DIM];

// ---------------- helpers ---------------------------------------------------
__device__ __forceinline__ uint32_t smem_u32(const void* p) {
    uint32_t a;
    asm("{ .reg .u64 t; cvta.to.shared.u64 t, %1; cvt.u32.u64 %0, t; }" : "=r"(a) : "l"(p));
    return a;
}
__device__ __forceinline__ float tf32_rna(float x) {
    uint32_t u;
    asm("cvt.rna.tf32.f32 %0, %1;" : "=r"(u) : "f"(x));
    return __uint_as_float(u);
}
__device__ __forceinline__ void mma_tf32(float& d0, float& d1, float& d2, float& d3,
                                         uint32_t a0, uint32_t a1, uint32_t a2, uint32_t a3,
                                         uint32_t b0, uint32_t b1) {
    asm("mma.sync.aligned.m16n8k8.row.col.f32.tf32.tf32.f32 "
        "{%0,%1,%2,%3},{%4,%5,%6,%7},{%8,%9},{%0,%1,%2,%3};\n"
        : "+f"(d0), "+f"(d1), "+f"(d2), "+f"(d3)
        : "r"(a0), "r"(a1), "r"(a2), "r"(a3), "r"(b0), "r"(b1));
}

#define CP_ASYNC16(dst, src) \
    asm volatile("cp.async.cg.shared.global [%0], [%1], 16;" :: "r"(dst), "l"(src) : "memory")
#define CP_COMMIT() asm volatile("cp.async.commit_group;" ::: "memory")
#define CP_WAIT1()  asm volatile("cp.async.wait_group 1;" ::: "memory")

// ---------------- prep kernels ----------------------------------------------
__global__ void prep_weights6(const float* __restrict__ sw1, const float* __restrict__ sw2,
                              const float* __restrict__ sw3, const float* __restrict__ tw1,
                              const float* __restrict__ tw2, const float* __restrict__ tw3,
                              const float* __restrict__ m1, const float* __restrict__ m2,
                              const float* __restrict__ m3, float* __restrict__ dst) {
    const size_t WSZ = 1024u * 1024u;
    int i = blockIdx.x * blockDim.x + threadIdx.x;   // over 262144 float4
    float4 a1 = reinterpret_cast<const float4*>(m1)[i];
    float4 a2 = reinterpret_cast<const float4*>(m2)[i];
    float4 a3 = reinterpret_cast<const float4*>(m3)[i];
#define DO_W(wp, mk, slot) { \
        float4 wv = reinterpret_cast<const float4*>(wp)[i]; \
        float4 o; \
        o.x = tf32_rna(wv.x * mk.x); o.y = tf32_rna(wv.y * mk.y); \
        o.z = tf32_rna(wv.z * mk.z); o.w = tf32_rna(wv.w * mk.w); \
        reinterpret_cast<float4*>(dst + (slot) * WSZ)[i] = o; }
    DO_W(sw1, a1, 0); DO_W(sw2, a2, 1); DO_W(sw3, a3, 2);
    DO_W(tw1, a1, 3); DO_W(tw2, a2, 4); DO_W(tw3, a3, 5);
#undef DO_W
}

__global__ void prep_x_kernel(const float* __restrict__ x, float* __restrict__ dst) {
    int i = blockIdx.x * blockDim.x + threadIdx.x;
    float4 v = reinterpret_cast<const float4*>(x)[i];
    float4 o;
    o.x = tf32_rna(v.x); o.y = tf32_rna(v.y); o.z = tf32_rna(v.z); o.w = tf32_rna(v.w);
    reinterpret_cast<float4*>(dst)[i] = o;
}

// ---------------- GEMM: C = act(A @ W^T + bias) -----------------------------
// CTA tile 128x128, BK=32, 128 threads = 4 warps (2x2), warp tile 64x64.
// 3-stage cp.async pipeline; smem rows padded to 36 floats.
#define ACT_TANH 0
#define ACT_RELU 1
#define ACT_NONE 2

#define NCH 32                       // K / BK
#define STAGES 3
#define SPAD 36                      // floats per smem row
#define STAGE_FLOATS (256 * SPAD)    // A(128 rows) + B(128 rows)
#define STAGE_BYTES  (STAGE_FLOATS * 4)          // 36864
#define GEMM_SMEM    (STAGES * STAGE_BYTES)      // 110592

template <int ACT>
__global__ __launch_bounds__(128, 2)
void gemm_tc_kernel(const float* __restrict__ A, const float* __restrict__ W,
                    const float* __restrict__ bias, float* __restrict__ C) {
    extern __shared__ __align__(16) float sm[];
    const uint32_t sbase = smem_u32(sm);

    const int tid   = threadIdx.x;
    const int warp  = tid >> 5;
    const int lane  = tid & 31;
    const int warpM = warp >> 1;         // 0..1 -> 64 rows
    const int warpN = warp & 1;          // 0..1 -> 64 cols
    const int qr    = lane >> 2;         // 0..7
    const int qc    = lane & 3;          // 0..3

    const int rowA0 = blockIdx.y * 128;  // batch rows
    const int colB0 = blockIdx.x * 128;  // output features

    float acc[4][8][4];
#pragma unroll
    for (int mf = 0; mf < 4; ++mf)
#pragma unroll
        for (int nf = 0; nf < 8; ++nf)
#pragma unroll
            for (int r = 0; r < 4; ++r) acc[mf][nf][r] = 0.f;

    // per-thread cp.async slots: 8 for A (128x8 float4), 8 for B
    uint32_t soff[16];
    const float* gp[16];
#pragma unroll
    for (int i = 0; i < 8; ++i) {
        int idx = tid + i * 128;             // 0..1023
        int r = idx >> 3, c4 = idx & 7;
        soff[i]     = (uint32_t)((r * SPAD + c4 * 4) * 4);
        gp[i]       = A + (size_t)(rowA0 + r) * DIM + c4 * 4;
        soff[8 + i] = (uint32_t)(((128 + r) * SPAD + c4 * 4) * 4);
        gp[8 + i]   = W + (size_t)(colB0 + r) * DIM + c4 * 4;
    }

#define LOAD_CHUNK(kt, st) do {                                             \
        uint32_t _b = sbase + (uint32_t)(st) * STAGE_BYTES;                 \
        int _ko = (kt) * 32;                                                \
        _Pragma("unroll")                                                   \
        for (int _i = 0; _i < 16; ++_i)                                     \
            CP_ASYNC16(_b + soff[_i], gp[_i] + _ko);                        \
    } while (0)

    // Prologue: prefetch chunks 0 and 1
    LOAD_CHUNK(0, 0); CP_COMMIT();
    LOAD_CHUNK(1, 1); CP_COMMIT();

    int st_c = 0;                            // stage of chunk kt
    for (int kt = 0; kt < NCH; ++kt) {
        CP_WAIT1();                          // chunk kt landed (kt+1 may fly)
        __syncthreads();                     // data visible; all warps done kt-1

        // prefetch chunk kt+2 into the stage freed by chunk kt-1
        if (kt + 2 < NCH) {
            int st_n = st_c + 2; if (st_n >= STAGES) st_n -= STAGES;
            LOAD_CHUNK(kt + 2, st_n);
        }
        CP_COMMIT();                         // exactly one group per iteration

        const float* As = sm + st_c * STAGE_FLOATS;
        const float* Bs = As + 128 * SPAD;
#pragma unroll
        for (int kk = 0; kk < 32; kk += 8) {
            uint32_t afr[4][4];
            uint32_t bfr[8][2];
#pragma unroll
            for (int mf = 0; mf < 4; ++mf) {
                int r0 = warpM * 64 + mf * 16 + qr;
                afr[mf][0] = __float_as_uint(As[(r0    ) * SPAD + kk + qc    ]);
                afr[mf][1] = __float_as_uint(As[(r0 + 8) * SPAD + kk + qc    ]);
                afr[mf][2] = __float_as_uint(As[(r0    ) * SPAD + kk + qc + 4]);
                afr[mf][3] = __float_as_uint(As[(r0 + 8) * SPAD + kk + qc + 4]);
            }
#pragma unroll
            for (int nf = 0; nf < 8; ++nf) {
                int n0 = warpN * 64 + nf * 8 + qr;
                bfr[nf][0] = __float_as_uint(Bs[n0 * SPAD + kk + qc    ]);
                bfr[nf][1] = __float_as_uint(Bs[n0 * SPAD + kk + qc + 4]);
            }
#pragma unroll
            for (int mf = 0; mf < 4; ++mf)
#pragma unroll
                for (int nf = 0; nf < 8; ++nf)
                    mma_tf32(acc[mf][nf][0], acc[mf][nf][1], acc[mf][nf][2], acc[mf][nf][3],
                             afr[mf][0], afr[mf][1], afr[mf][2], afr[mf][3],
                             bfr[nf][0], bfr[nf][1]);
        }
        ++st_c; if (st_c >= STAGES) st_c = 0;
    }

    // ---- epilogue: bias + activation (+ tf32 requantize for intermediates) ----
#pragma unroll
    for (int mf = 0; mf < 4; ++mf) {
#pragma unroll
        for (int nf = 0; nf < 8; ++nf) {
            int row0 = rowA0 + warpM * 64 + mf * 16 + qr;
            int col0 = colB0 + warpN * 64 + nf * 8 + 2 * qc;
            float b0 = bias[col0];
            float b1 = bias[col0 + 1];
            float v0 = acc[mf][nf][0] + b0;
            float v1 = acc[mf][nf][1] + b1;
            float v2 = acc[mf][nf][2] + b0;
            float v3 = acc[mf][nf][3] + b1;
            if (ACT == ACT_TANH) {
                v0 = tf32_rna(tanhf(v0)); v1 = tf32_rna(tanhf(v1));
                v2 = tf32_rna(tanhf(v2)); v3 = tf32_rna(tanhf(v3));
            } else if (ACT == ACT_RELU) {
                v0 = tf32_rna(fmaxf(v0, 0.f)); v1 = tf32_rna(fmaxf(v1, 0.f));
                v2 = tf32_rna(fmaxf(v2, 0.f)); v3 = tf32_rna(fmaxf(v3, 0.f));
            }
            *reinterpret_cast<float2*>(C + (size_t)row0 * DIM + col0)       = make_float2(v0, v1);
            *reinterpret_cast<float2*>(C + (size_t)(row0 + 8) * DIM + col0) = make_float2(v2, v3);
        }
    }
}

// ---------------- final elementwise + logdet --------------------------------
__global__ void final_kernel(const float* __restrict__ x, const float* __restrict__ m,
                             const float* __restrict__ a, float* __restrict__ out) {
    int b = blockIdx.x;
    int t = threadIdx.x;
    size_t base = (size_t)b * DIM;
    float s = 0.f;
#pragma unroll
    for (int i = 0; i < 4; ++i) {
        int c = t + i * 256;
        float av = a[base + c];
        float mv = m[base + c];
        float xv = x[base + c];
        out[base + c] = (xv - mv) * expf(-av);
        s += av;
    }
#pragma unroll
    for (int o = 16; o; o >>= 1) s += __shfl_down_sync(0xFFFFFFFFu, s, o);
    __shared__ float ws[8];
    if ((t & 31) == 0) ws[t >> 5] = s;
    __syncthreads();
    if (t < 8) {
        float v = ws[t];
#pragma unroll
        for (int o = 4; o; o >>= 1) v += __shfl_down_sync(0xFFu, v, o);
        if (t == 0) out[(size_t)BATCH * DIM + b] = -v;
    }
}

// ---------------- launcher ---------------------------------------------------
extern "C" void kernel_launch(void* const* d_in, const int* in_sizes, int n_in,
                              void* d_out, int out_size) {
    (void)in_sizes; (void)n_in; (void)out_size;
    const float* x      = (const float*)d_in[0];
    const float* s_w1   = (const float*)d_in[1];
    const float* s_b1   = (const float*)d_in[2];
    const float* s_w2   = (const float*)d_in[3];
    const float* s_b2   = (const float*)d_in[4];
    const float* s_w3   = (const float*)d_in[5];
    const float* s_b3   = (const float*)d_in[6];
    const float* t_w1   = (const float*)d_in[7];
    const float* t_b1   = (const float*)d_in[8];
    const float* t_w2   = (const float*)d_in[9];
    const float* t_b2   = (const float*)d_in[10];
    const float* t_w3   = (const float*)d_in[11];
    const float* t_b3   = (const float*)d_in[12];
    const float* mask_in  = (const float*)d_in[13];
    const float* mask_hid = (const float*)d_in[14];
    const float* mask_out = (const float*)d_in[15];
    float* out = (float*)d_out;

    float *wm, *x32, *h1, *h2, *mbuf, *abuf;
    cudaGetSymbolAddress((void**)&wm,   g_wm);
    cudaGetSymbolAddress((void**)&x32,  g_x32);
    cudaGetSymbolAddress((void**)&h1,   g_h1);
    cudaGetSymbolAddress((void**)&h2,   g_h2);
    cudaGetSymbolAddress((void**)&mbuf, g_m);
    cudaGetSymbolAddress((void**)&abuf, g_a);

    const size_t WSZ = 1024u * 1024u;

    cudaFuncSetAttribute(gemm_tc_kernel<ACT_TANH>,
                         cudaFuncAttributeMaxDynamicSharedMemorySize, GEMM_SMEM);
    cudaFuncSetAttribute(gemm_tc_kernel<ACT_RELU>,
                         cudaFuncAttributeMaxDynamicSharedMemorySize, GEMM_SMEM);
    cudaFuncSetAttribute(gemm_tc_kernel<ACT_NONE>,
                         cudaFuncAttributeMaxDynamicSharedMemorySize, GEMM_SMEM);

    prep_weights6<<<1024, 256>>>(s_w1, s_w2, s_w3, t_w1, t_w2, t_w3,
                                 mask_in, mask_hid, mask_out, wm);
    prep_x_kernel<<<4096, 256>>>(x, x32);

    dim3 grid(DIM / 128, BATCH / 128);   // (8, 32) = 256 CTAs, one wave @2/SM
    // s branch (tanh)
    gemm_tc_kernel<ACT_TANH><<<grid, 128, GEMM_SMEM>>>(x32, wm + 0 * WSZ, s_b1, h1);
    gemm_tc_kernel<ACT_TANH><<<grid, 128, GEMM_SMEM>>>(h1,  wm + 1 * WSZ, s_b2, h2);
    gemm_tc_kernel<ACT_NONE><<<grid, 128, GEMM_SMEM>>>(h2,  wm + 2 * WSZ, s_b3, mbuf);
    // t branch (relu)
    gemm_tc_kernel<ACT_RELU><<<grid, 128, GEMM_SMEM>>>(x32, wm + 3 * WSZ, t_b1, h1);
    gemm_tc_kernel<ACT_RELU><<<grid, 128, GEMM_SMEM>>>(h1,  wm + 4 * WSZ, t_b2, h2);
    gemm_tc_kernel<ACT_NONE><<<grid, 128, GEMM_SMEM>>>(h2,  wm + 5 * WSZ, t_b3, abuf);

    final_kernel<<<BATCH, 256>>>(x, mbuf, abuf, out);
}

// round 4
// speedup vs baseline: 1.9984x; 1.8665x over previous
#include <cuda_runtime.h>
#include <cuda_fp16.h>
#include <cstdint>
#include <cstddef>

#define BATCH 4096
#define DIM   1024

// ---------------- scratch (static device memory) ----------------------------
__device__ __half g_wm16[6u * 1024u * 1024u];  // fp16 masked weights
__device__ __half g_x16 [BATCH * DIM];         // fp16 input copy
__device__ __half g_h1  [BATCH * DIM];
__device__ __half g_h2  [BATCH * DIM];
__device__ float  g_m   [BATCH * DIM];
__device__ float  g_a   [BATCH * DIM];

// ---------------- helpers ---------------------------------------------------
__device__ __forceinline__ uint32_t smem_u32(const void* p) {
    uint32_t a;
    asm("{ .reg .u64 t; cvta.to.shared.u64 t, %1; cvt.u32.u64 %0, t; }" : "=r"(a) : "l"(p));
    return a;
}

__device__ __forceinline__ void ldm_x4(uint32_t& r0, uint32_t& r1, uint32_t& r2, uint32_t& r3,
                                       uint32_t addr) {
    asm volatile("ldmatrix.sync.aligned.m8n8.x4.shared.b16 {%0,%1,%2,%3}, [%4];"
                 : "=r"(r0), "=r"(r1), "=r"(r2), "=r"(r3) : "r"(addr));
}

__device__ __forceinline__ void mma_f16(float& d0, float& d1, float& d2, float& d3,
                                        uint32_t a0, uint32_t a1, uint32_t a2, uint32_t a3,
                                        uint32_t b0, uint32_t b1) {
    asm("mma.sync.aligned.m16n8k16.row.col.f32.f16.f16.f32 "
        "{%0,%1,%2,%3},{%4,%5,%6,%7},{%8,%9},{%0,%1,%2,%3};\n"
        : "+f"(d0), "+f"(d1), "+f"(d2), "+f"(d3)
        : "r"(a0), "r"(a1), "r"(a2), "r"(a3), "r"(b0), "r"(b1));
}

#define CP_ASYNC16(dst, src) \
    asm volatile("cp.async.cg.shared.global [%0], [%1], 16;" :: "r"(dst), "l"(src) : "memory")
#define CP_COMMIT() asm volatile("cp.async.commit_group;" ::: "memory")
#define CP_WAIT1()  asm volatile("cp.async.wait_group 1;" ::: "memory")

// ---------------- prep kernels ----------------------------------------------
__global__ void prep_weights6(const float* __restrict__ sw1, const float* __restrict__ sw2,
                              const float* __restrict__ sw3, const float* __restrict__ tw1,
                              const float* __restrict__ tw2, const float* __restrict__ tw3,
                              const float* __restrict__ m1, const float* __restrict__ m2,
                              const float* __restrict__ m3, __half* __restrict__ dst) {
    const size_t WSZ = 1024u * 1024u;
    int i = blockIdx.x * blockDim.x + threadIdx.x;   // over 262144 float4
    float4 a1 = reinterpret_cast<const float4*>(m1)[i];
    float4 a2 = reinterpret_cast<const float4*>(m2)[i];
    float4 a3 = reinterpret_cast<const float4*>(m3)[i];
#define DO_W(wp, mk, slot) { \
        float4 wv = reinterpret_cast<const float4*>(wp)[i]; \
        __half2* d2 = reinterpret_cast<__half2*>(dst + (slot) * WSZ); \
        d2[2 * i]     = __floats2half2_rn(wv.x * mk.x, wv.y * mk.y); \
        d2[2 * i + 1] = __floats2half2_rn(wv.z * mk.z, wv.w * mk.w); }
    DO_W(sw1, a1, 0); DO_W(sw2, a2, 1); DO_W(sw3, a3, 2);
    DO_W(tw1, a1, 3); DO_W(tw2, a2, 4); DO_W(tw3, a3, 5);
#undef DO_W
}

__global__ void prep_x_kernel(const float* __restrict__ x, __half* __restrict__ dst) {
    int i = blockIdx.x * blockDim.x + threadIdx.x;
    float4 v = reinterpret_cast<const float4*>(x)[i];
    __half2* d2 = reinterpret_cast<__half2*>(dst);
    d2[2 * i]     = __floats2half2_rn(v.x, v.y);
    d2[2 * i + 1] = __floats2half2_rn(v.z, v.w);
}

// ---------------- GEMM: C = act(A @ W^T + bias) -----------------------------
// fp16 inputs, fp32 accumulate. CTA tile 128x128, BK=64 halves, 4 warps (2x2),
// warp tile 64x64. 3-stage cp.async pipeline; smem rows padded to 144B.
#define ACT_TANH 0
#define ACT_RELU 1
#define ACT_NONE 2

#define NCH 16                        // K / BK = 1024 / 64
#define STAGES 3
#define ROWB 144                      // bytes per padded smem row (64 halves + pad)
#define STAGE_BYTES (256 * ROWB)      // A(128 rows) + B(128 rows) = 36864
#define B_SMEM_OFF  (128 * ROWB)      // 18432
#define GEMM_SMEM   (STAGES * STAGE_BYTES)   // 110592

template <int ACT, typename OutT>
__global__ __launch_bounds__(128, 2)
void gemm_f16_kernel(const __half* __restrict__ A, const __half* __restrict__ W,
                     const float* __restrict__ bias, OutT* __restrict__ C) {
    extern __shared__ __align__(16) char smc[];
    const uint32_t sbase = smem_u32(smc);

    const int tid   = threadIdx.x;
    const int warp  = tid >> 5;
    const int lane  = tid & 31;
    const int warpM = warp >> 1;         // 0..1 -> 64 rows
    const int warpN = warp & 1;          // 0..1 -> 64 cols
    const int qr    = lane >> 2;         // 0..7
    const int qc    = lane & 3;          // 0..3

    const int rowA0 = blockIdx.y * 128;
    const int colB0 = blockIdx.x * 128;

    float acc[4][8][4];
#pragma unroll
    for (int mf = 0; mf < 4; ++mf)
#pragma unroll
        for (int nf = 0; nf < 8; ++nf)
#pragma unroll
            for (int r = 0; r < 4; ++r) acc[mf][nf][r] = 0.f;

    // ---- cp.async slot bases (slot i = base + i*16 rows) ----
    const int r0 = tid >> 3;             // 0..15
    const int c  = tid & 7;              // 16B column within 128B row
    const __half* gA = A + (size_t)(rowA0 + r0) * DIM + c * 8;
    const __half* gB = W + (size_t)(colB0 + r0) * DIM + c * 8;
    const uint32_t sA = (uint32_t)(r0 * ROWB + c * 16);
    const uint32_t sB = (uint32_t)(B_SMEM_OFF + r0 * ROWB + c * 16);

#define LOAD_CHUNK(kt, st) do {                                              \
        uint32_t _b = sbase + (uint32_t)(st) * STAGE_BYTES;                  \
        const __half* _ga = gA + (kt) * 64;                                  \
        const __half* _gb = gB + (kt) * 64;                                  \
        _Pragma("unroll")                                                    \
        for (int _i = 0; _i < 8; ++_i) {                                     \
            CP_ASYNC16(_b + sA + _i * (16 * ROWB), _ga + _i * (16 * DIM));   \
            CP_ASYNC16(_b + sB + _i * (16 * ROWB), _gb + _i * (16 * DIM));   \
        }                                                                    \
    } while (0)

    // ---- ldmatrix per-thread base offsets ----
    // A fragment (m16k16): lanes 0-7 rows 0-7 k0; 8-15 rows 8-15 k0;
    //                      16-23 rows 0-7 k8; 24-31 rows 8-15 k8.
    uint32_t aoff[4], boff[4];
#pragma unroll
    for (int mf = 0; mf < 4; ++mf) {
        int arow = warpM * 64 + mf * 16 + (lane & 15);
        aoff[mf] = (uint32_t)(arow * ROWB + ((lane >> 4) & 1) * 16);
    }
    // B fragment (two n8k16 tiles): lanes 0-7 n0-7 k0; 8-15 n0-7 k8;
    //                               16-23 n8-15 k0; 24-31 n8-15 k8.
#pragma unroll
    for (int np = 0; np < 4; ++np) {
        int brow = warpN * 64 + np * 16 + (lane & 7) + ((lane >> 4) & 1) * 8;
        boff[np] = (uint32_t)(B_SMEM_OFF + brow * ROWB + ((lane >> 3) & 1) * 16);
    }

    // Prologue: prefetch chunks 0 and 1
    LOAD_CHUNK(0, 0); CP_COMMIT();
    LOAD_CHUNK(1, 1); CP_COMMIT();

    uint32_t afr[2][4][4];
    uint32_t bfr[2][8][2];

    int st_c = 0;
    for (int kt = 0; kt < NCH; ++kt) {
        CP_WAIT1();
        __syncthreads();

        if (kt + 2 < NCH) {
            int st_n = st_c + 2; if (st_n >= STAGES) st_n -= STAGES;
            LOAD_CHUNK(kt + 2, st_n);
        }
        CP_COMMIT();

        const uint32_t stb = sbase + (uint32_t)st_c * STAGE_BYTES;

#define LOAD_FRAGS(buf, kk) do {                                                     \
        _Pragma("unroll")                                                            \
        for (int _mf = 0; _mf < 4; ++_mf)                                            \
            ldm_x4(afr[buf][_mf][0], afr[buf][_mf][1], afr[buf][_mf][2],             \
                   afr[buf][_mf][3], stb + aoff[_mf] + (kk) * 2);                    \
        _Pragma("unroll")                                                            \
        for (int _np = 0; _np < 4; ++_np)                                            \
            ldm_x4(bfr[buf][2 * _np][0], bfr[buf][2 * _np][1],                       \
                   bfr[buf][2 * _np + 1][0], bfr[buf][2 * _np + 1][1],               \
                   stb + boff[_np] + (kk) * 2);                                      \
    } while (0)

        LOAD_FRAGS(0, 0);
#pragma unroll
        for (int s = 0; s < 4; ++s) {      // k-steps of 16 within 64-chunk
            const int cur = s & 1;
            if (s < 3) LOAD_FRAGS(!cur, (s + 1) * 16);
#pragma unroll
            for (int mf = 0; mf < 4; ++mf)
#pragma unroll
                for (int nf = 0; nf < 8; ++nf)
                    mma_f16(acc[mf][nf][0], acc[mf][nf][1], acc[mf][nf][2], acc[mf][nf][3],
                            afr[cur][mf][0], afr[cur][mf][1], afr[cur][mf][2], afr[cur][mf][3],
                            bfr[cur][nf][0], bfr[cur][nf][1]);
        }
#undef LOAD_FRAGS
        ++st_c; if (st_c >= STAGES) st_c = 0;
    }

    // ---- epilogue: bias + activation; fp16 store for intermediates ----
#pragma unroll
    for (int mf = 0; mf < 4; ++mf) {
#pragma unroll
        for (int nf = 0; nf < 8; ++nf) {
            int row0 = rowA0 + warpM * 64 + mf * 16 + qr;
            int col0 = colB0 + warpN * 64 + nf * 8 + 2 * qc;
            float b0 = bias[col0];
            float b1 = bias[col0 + 1];
            float v0 = acc[mf][nf][0] + b0;
            float v1 = acc[mf][nf][1] + b1;
            float v2 = acc[mf][nf][2] + b0;
            float v3 = acc[mf][nf][3] + b1;
            if (ACT == ACT_TANH) {
                v0 = tanhf(v0); v1 = tanhf(v1); v2 = tanhf(v2); v3 = tanhf(v3);
            } else if (ACT == ACT_RELU) {
                v0 = fmaxf(v0, 0.f); v1 = fmaxf(v1, 0.f);
                v2 = fmaxf(v2, 0.f); v3 = fmaxf(v3, 0.f);
            }
            if (sizeof(OutT) == 2) {   // __half intermediate
                __half2* p0 = reinterpret_cast<__half2*>((__half*)C + (size_t)row0 * DIM + col0);
                __half2* p1 = reinterpret_cast<__half2*>((__half*)C + (size_t)(row0 + 8) * DIM + col0);
                *p0 = __floats2half2_rn(v0, v1);
                *p1 = __floats2half2_rn(v2, v3);
            } else {                    // float output (m / a)
                *reinterpret_cast<float2*>((float*)C + (size_t)row0 * DIM + col0)       = make_float2(v0, v1);
                *reinterpret_cast<float2*>((float*)C + (size_t)(row0 + 8) * DIM + col0) = make_float2(v2, v3);
            }
        }
    }
}

// ---------------- final elementwise + logdet --------------------------------
__global__ void final_kernel(const float* __restrict__ x, const float* __restrict__ m,
                             const float* __restrict__ a, float* __restrict__ out) {
    int b = blockIdx.x;
    int t = threadIdx.x;
    size_t base = (size_t)b * DIM;
    float s = 0.f;
#pragma unroll
    for (int i = 0; i < 4; ++i) {
        int c = t + i * 256;
        float av = a[base + c];
        float mv = m[base + c];
        float xv = x[base + c];
        out[base + c] = (xv - mv) * expf(-av);
        s += av;
    }
#pragma unroll
    for (int o = 16; o; o >>= 1) s += __shfl_down_sync(0xFFFFFFFFu, s, o);
    __shared__ float ws[8];
    if ((t & 31) == 0) ws[t >> 5] = s;
    __syncthreads();
    if (t < 8) {
        float v = ws[t];
#pragma unroll
        for (int o = 4; o; o >>= 1) v += __shfl_down_sync(0xFFu, v, o);
        if (t == 0) out[(size_t)BATCH * DIM + b] = -v;
    }
}

// ---------------- launcher ---------------------------------------------------
extern "C" void kernel_launch(void* const* d_in, const int* in_sizes, int n_in,
                              void* d_out, int out_size) {
    (void)in_sizes; (void)n_in; (void)out_size;
    const float* x      = (const float*)d_in[0];
    const float* s_w1   = (const float*)d_in[1];
    const float* s_b1   = (const float*)d_in[2];
    const float* s_w2   = (const float*)d_in[3];
    const float* s_b2   = (const float*)d_in[4];
    const float* s_w3   = (const float*)d_in[5];
    const float* s_b3   = (const float*)d_in[6];
    const float* t_w1   = (const float*)d_in[7];
    const float* t_b1   = (const float*)d_in[8];
    const float* t_w2   = (const float*)d_in[9];
    const float* t_b2   = (const float*)d_in[10];
    const float* t_w3   = (const float*)d_in[11];
    const float* t_b3   = (const float*)d_in[12];
    const float* mask_in  = (const float*)d_in[13];
    const float* mask_hid = (const float*)d_in[14];
    const float* mask_out = (const float*)d_in[15];
    float* out = (float*)d_out;

    __half *wm, *x16, *h1, *h2;
    float *mbuf, *abuf;
    cudaGetSymbolAddress((void**)&wm,   g_wm16);
    cudaGetSymbolAddress((void**)&x16,  g_x16);
    cudaGetSymbolAddress((void**)&h1,   g_h1);
    cudaGetSymbolAddress((void**)&h2,   g_h2);
    cudaGetSymbolAddress((void**)&mbuf, g_m);
    cudaGetSymbolAddress((void**)&abuf, g_a);

    const size_t WSZ = 1024u * 1024u;

    cudaFuncSetAttribute((const void*)gemm_f16_kernel<ACT_TANH, __half>,
                         cudaFuncAttributeMaxDynamicSharedMemorySize, GEMM_SMEM);
    cudaFuncSetAttribute((const void*)gemm_f16_kernel<ACT_RELU, __half>,
                         cudaFuncAttributeMaxDynamicSharedMemorySize, GEMM_SMEM);
    cudaFuncSetAttribute((const void*)gemm_f16_kernel<ACT_NONE, float>,
                         cudaFuncAttributeMaxDynamicSharedMemorySize, GEMM_SMEM);

    prep_weights6<<<1024, 256>>>(s_w1, s_w2, s_w3, t_w1, t_w2, t_w3,
                                 mask_in, mask_hid, mask_out, wm);
    prep_x_kernel<<<4096, 256>>>(x, x16);

    dim3 grid(DIM / 128, BATCH / 128);   // (8, 32) = 256 CTAs
    // s branch (tanh)
    gemm_f16_kernel<ACT_TANH, __half><<<grid, 128, GEMM_SMEM>>>(x16, wm + 0 * WSZ, s_b1, h1);
    gemm_f16_kernel<ACT_TANH, __half><<<grid, 128, GEMM_SMEM>>>(h1,  wm + 1 * WSZ, s_b2, h2);
    gemm_f16_kernel<ACT_NONE, float ><<<grid, 128, GEMM_SMEM>>>(h2,  wm + 2 * WSZ, s_b3, mbuf);
    // t branch (relu)
    gemm_f16_kernel<ACT_RELU, __half><<<grid, 128, GEMM_SMEM>>>(x16, wm + 3 * WSZ, t_b1, h1);
    gemm_f16_kernel<ACT_RELU, __half><<<grid, 128, GEMM_SMEM>>>(h1,  wm + 4 * WSZ, t_b2, h2);
    gemm_f16_kernel<ACT_NONE, float ><<<grid, 128, GEMM_SMEM>>>(h2,  wm + 5 * WSZ, t_b3, abuf);

    final_kernel<<<BATCH, 256>>>(x, mbuf, abuf, out);
}

// round 5
// speedup vs baseline: 2.0183x; 1.0100x over previous
#include <cuda_runtime.h>
#include <cuda_fp16.h>
#include <cstdint>
#include <cstddef>

#define BATCH 4096
#define DIM   1024

// ---------------- scratch (static device memory) ----------------------------
__device__ __half g_wm16[6u * 1024u * 1024u];  // fp16 masked weights
__device__ __half g_x16 [BATCH * DIM];         // fp16 input copy
__device__ __half g_h1  [BATCH * DIM];
__device__ __half g_h2  [BATCH * DIM];
__device__ float  g_m   [BATCH * DIM];
__device__ float  g_a   [BATCH * DIM];

// ---------------- helpers ---------------------------------------------------
__device__ __forceinline__ uint32_t smem_u32(const void* p) {
    uint32_t a;
    asm("{ .reg .u64 t; cvta.to.shared.u64 t, %1; cvt.u32.u64 %0, t; }" : "=r"(a) : "l"(p));
    return a;
}

__device__ __forceinline__ void ldm_x4(uint32_t& r0, uint32_t& r1, uint32_t& r2, uint32_t& r3,
                                       uint32_t addr) {
    asm volatile("ldmatrix.sync.aligned.m8n8.x4.shared.b16 {%0,%1,%2,%3}, [%4];"
                 : "=r"(r0), "=r"(r1), "=r"(r2), "=r"(r3) : "r"(addr));
}

__device__ __forceinline__ void mma_f16(float& d0, float& d1, float& d2, float& d3,
                                        uint32_t a0, uint32_t a1, uint32_t a2, uint32_t a3,
                                        uint32_t b0, uint32_t b1) {
    asm("mma.sync.aligned.m16n8k16.row.col.f32.f16.f16.f32 "
        "{%0,%1,%2,%3},{%4,%5,%6,%7},{%8,%9},{%0,%1,%2,%3};\n"
        : "+f"(d0), "+f"(d1), "+f"(d2), "+f"(d3)
        : "r"(a0), "r"(a1), "r"(a2), "r"(a3), "r"(b0), "r"(b1));
}

#define CP_ASYNC16(dst, src) \
    asm volatile("cp.async.cg.shared.global [%0], [%1], 16;" :: "r"(dst), "l"(src) : "memory")
#define CP_COMMIT() asm volatile("cp.async.commit_group;" ::: "memory")
#define CP_WAIT1()  asm volatile("cp.async.wait_group 1;" ::: "memory")

// ---------------- prep kernels ----------------------------------------------
__global__ void prep_weights6(const float* __restrict__ sw1, const float* __restrict__ sw2,
                              const float* __restrict__ sw3, const float* __restrict__ tw1,
                              const float* __restrict__ tw2, const float* __restrict__ tw3,
                              const float* __restrict__ m1, const float* __restrict__ m2,
                              const float* __restrict__ m3, __half* __restrict__ dst) {
    const size_t WSZ = 1024u * 1024u;
    int i = blockIdx.x * blockDim.x + threadIdx.x;   // over 262144 float4
    float4 a1 = reinterpret_cast<const float4*>(m1)[i];
    float4 a2 = reinterpret_cast<const float4*>(m2)[i];
    float4 a3 = reinterpret_cast<const float4*>(m3)[i];
#define DO_W(wp, mk, slot) { \
        float4 wv = reinterpret_cast<const float4*>(wp)[i]; \
        __half2* d2 = reinterpret_cast<__half2*>(dst + (slot) * WSZ); \
        d2[2 * i]     = __floats2half2_rn(wv.x * mk.x, wv.y * mk.y); \
        d2[2 * i + 1] = __floats2half2_rn(wv.z * mk.z, wv.w * mk.w); }
    DO_W(sw1, a1, 0); DO_W(sw2, a2, 1); DO_W(sw3, a3, 2);
    DO_W(tw1, a1, 3); DO_W(tw2, a2, 4); DO_W(tw3, a3, 5);
#undef DO_W
}

__global__ void prep_x_kernel(const float* __restrict__ x, __half* __restrict__ dst) {
    int i = blockIdx.x * blockDim.x + threadIdx.x;
    float4 v = reinterpret_cast<const float4*>(x)[i];
    __half2* d2 = reinterpret_cast<__half2*>(dst);
    d2[2 * i]     = __floats2half2_rn(v.x, v.y);
    d2[2 * i + 1] = __floats2half2_rn(v.z, v.w);
}

// ---------------- GEMM: C = act(A @ W^T + bias) -----------------------------
// fp16 in, fp32 acc. CTA tile 128x128, BK=64 halves, 256 threads = 8 warps
// (2 x 4), warp tile 64x32. 3-stage cp.async pipeline; rows padded to 144B.
#define ACT_TANH 0
#define ACT_RELU 1
#define ACT_NONE 2

#define NCH 16                        // K / BK = 1024 / 64
#define STAGES 3
#define ROWB 144                      // bytes per padded smem row
#define STAGE_BYTES (256 * ROWB)      // 36864
#define B_SMEM_OFF  (128 * ROWB)      // 18432
#define GEMM_SMEM   (STAGES * STAGE_BYTES)   // 110592

template <int ACT, typename OutT>
__global__ __launch_bounds__(256, 2)
void gemm_f16_kernel(const __half* __restrict__ A, const __half* __restrict__ W,
                     const float* __restrict__ bias, OutT* __restrict__ C) {
    extern __shared__ __align__(16) char smc[];
    const uint32_t sbase = smem_u32(smc);

    const int tid   = threadIdx.x;
    const int warp  = tid >> 5;
    const int lane  = tid & 31;
    const int warpM = warp >> 2;         // 0..1 -> 64 rows
    const int warpN = warp & 3;          // 0..3 -> 32 cols
    const int qr    = lane >> 2;         // 0..7
    const int qc    = lane & 3;          // 0..3

    const int rowA0 = blockIdx.y * 128;
    const int colB0 = blockIdx.x * 128;

    float acc[4][4][4];
#pragma unroll
    for (int mf = 0; mf < 4; ++mf)
#pragma unroll
        for (int nf = 0; nf < 4; ++nf)
#pragma unroll
            for (int r = 0; r < 4; ++r) acc[mf][nf][r] = 0.f;

    // ---- cp.async slot bases: 256 threads, 4 A slots + 4 B slots each ----
    const int r0 = tid >> 3;             // 0..31
    const int c  = tid & 7;              // 16B column within 128B row
    const __half* gA = A + (size_t)(rowA0 + r0) * DIM + c * 8;
    const __half* gB = W + (size_t)(colB0 + r0) * DIM + c * 8;
    const uint32_t sA = (uint32_t)(r0 * ROWB + c * 16);
    const uint32_t sB = (uint32_t)(B_SMEM_OFF + r0 * ROWB + c * 16);

#define LOAD_CHUNK(kt, st) do {                                              \
        uint32_t _b = sbase + (uint32_t)(st) * STAGE_BYTES;                  \
        const __half* _ga = gA + (kt) * 64;                                  \
        const __half* _gb = gB + (kt) * 64;                                  \
        _Pragma("unroll")                                                    \
        for (int _i = 0; _i < 4; ++_i) {                                     \
            CP_ASYNC16(_b + sA + _i * (32 * ROWB), _ga + _i * (32 * DIM));   \
            CP_ASYNC16(_b + sB + _i * (32 * ROWB), _gb + _i * (32 * DIM));   \
        }                                                                    \
    } while (0)

    // ---- ldmatrix per-thread base offsets ----
    uint32_t aoff[4], boff[2];
#pragma unroll
    for (int mf = 0; mf < 4; ++mf) {
        int arow = warpM * 64 + mf * 16 + (lane & 15);
        aoff[mf] = (uint32_t)(arow * ROWB + ((lane >> 4) & 1) * 16);
    }
#pragma unroll
    for (int np = 0; np < 2; ++np) {
        int brow = warpN * 32 + np * 16 + (lane & 7) + ((lane >> 4) & 1) * 8;
        boff[np] = (uint32_t)(B_SMEM_OFF + brow * ROWB + ((lane >> 3) & 1) * 16);
    }

    // Prologue: prefetch chunks 0 and 1
    LOAD_CHUNK(0, 0); CP_COMMIT();
    LOAD_CHUNK(1, 1); CP_COMMIT();

    int st_c = 0;
    for (int kt = 0; kt < NCH; ++kt) {
        CP_WAIT1();
        __syncthreads();

        if (kt + 2 < NCH) {
            int st_n = st_c + 2; if (st_n >= STAGES) st_n -= STAGES;
            LOAD_CHUNK(kt + 2, st_n);
        }
        CP_COMMIT();

        const uint32_t stb = sbase + (uint32_t)st_c * STAGE_BYTES;
#pragma unroll
        for (int s = 0; s < 4; ++s) {        // k16 steps within the 64-chunk
            uint32_t afr[4][4];
            uint32_t bfr[4][2];
#pragma unroll
            for (int mf = 0; mf < 4; ++mf)
                ldm_x4(afr[mf][0], afr[mf][1], afr[mf][2], afr[mf][3],
                       stb + aoff[mf] + s * 32);
#pragma unroll
            for (int np = 0; np < 2; ++np)
                ldm_x4(bfr[2 * np][0], bfr[2 * np][1],
                       bfr[2 * np + 1][0], bfr[2 * np + 1][1],
                       stb + boff[np] + s * 32);
#pragma unroll
            for (int mf = 0; mf < 4; ++mf)
#pragma unroll
                for (int nf = 0; nf < 4; ++nf)
                    mma_f16(acc[mf][nf][0], acc[mf][nf][1], acc[mf][nf][2], acc[mf][nf][3],
                            afr[mf][0], afr[mf][1], afr[mf][2], afr[mf][3],
                            bfr[nf][0], bfr[nf][1]);
        }
        ++st_c; if (st_c >= STAGES) st_c = 0;
    }

    // ---- epilogue: bias + activation; fp16 store for intermediates ----
#pragma unroll
    for (int mf = 0; mf < 4; ++mf) {
#pragma unroll
        for (int nf = 0; nf < 4; ++nf) {
            int row0 = rowA0 + warpM * 64 + mf * 16 + qr;
            int col0 = colB0 + warpN * 32 + nf * 8 + 2 * qc;
            float b0 = bias[col0];
            float b1 = bias[col0 + 1];
            float v0 = acc[mf][nf][0] + b0;
            float v1 = acc[mf][nf][1] + b1;
            float v2 = acc[mf][nf][2] + b0;
            float v3 = acc[mf][nf][3] + b1;
            if (ACT == ACT_TANH) {
                v0 = tanhf(v0); v1 = tanhf(v1); v2 = tanhf(v2); v3 = tanhf(v3);
            } else if (ACT == ACT_RELU) {
                v0 = fmaxf(v0, 0.f); v1 = fmaxf(v1, 0.f);
                v2 = fmaxf(v2, 0.f); v3 = fmaxf(v3, 0.f);
            }
            if (sizeof(OutT) == 2) {   // __half intermediate
                __half2* p0 = reinterpret_cast<__half2*>((__half*)C + (size_t)row0 * DIM + col0);
                __half2* p1 = reinterpret_cast<__half2*>((__half*)C + (size_t)(row0 + 8) * DIM + col0);
                *p0 = __floats2half2_rn(v0, v1);
                *p1 = __floats2half2_rn(v2, v3);
            } else {                    // float output (m / a)
                *reinterpret_cast<float2*>((float*)C + (size_t)row0 * DIM + col0)       = make_float2(v0, v1);
                *reinterpret_cast<float2*>((float*)C + (size_t)(row0 + 8) * DIM + col0) = make_float2(v2, v3);
            }
        }
    }
}

// ---------------- final elementwise + logdet --------------------------------
__global__ void final_kernel(const float* __restrict__ x, const float* __restrict__ m,
                             const float* __restrict__ a, float* __restrict__ out) {
    int b = blockIdx.x;
    int t = threadIdx.x;
    size_t base = (size_t)b * DIM;
    float s = 0.f;
#pragma unroll
    for (int i = 0; i < 4; ++i) {
        int c = t + i * 256;
        float av = a[base + c];
        float mv = m[base + c];
        float xv = x[base + c];
        out[base + c] = (xv - mv) * expf(-av);
        s += av;
    }
#pragma unroll
    for (int o = 16; o; o >>= 1) s += __shfl_down_sync(0xFFFFFFFFu, s, o);
    __shared__ float ws[8];
    if ((t & 31) == 0) ws[t >> 5] = s;
    __syncthreads();
    if (t < 8) {
        float v = ws[t];
#pragma unroll
        for (int o = 4; o; o >>= 1) v += __shfl_down_sync(0xFFu, v, o);
        if (t == 0) out[(size_t)BATCH * DIM + b] = -v;
    }
}

// ---------------- launcher ---------------------------------------------------
extern "C" void kernel_launch(void* const* d_in, const int* in_sizes, int n_in,
                              void* d_out, int out_size) {
    (void)in_sizes; (void)n_in; (void)out_size;
    const float* x      = (const float*)d_in[0];
    const float* s_w1   = (const float*)d_in[1];
    const float* s_b1   = (const float*)d_in[2];
    const float* s_w2   = (const float*)d_in[3];
    const float* s_b2   = (const float*)d_in[4];
    const float* s_w3   = (const float*)d_in[5];
    const float* s_b3   = (const float*)d_in[6];
    const float* t_w1   = (const float*)d_in[7];
    const float* t_b1   = (const float*)d_in[8];
    const float* t_w2   = (const float*)d_in[9];
    const float* t_b2   = (const float*)d_in[10];
    const float* t_w3   = (const float*)d_in[11];
    const float* t_b3   = (const float*)d_in[12];
    const float* mask_in  = (const float*)d_in[13];
    const float* mask_hid = (const float*)d_in[14];
    const float* mask_out = (const float*)d_in[15];
    float* out = (float*)d_out;

    __half *wm, *x16, *h1, *h2;
    float *mbuf, *abuf;
    cudaGetSymbolAddress((void**)&wm,   g_wm16);
    cudaGetSymbolAddress((void**)&x16,  g_x16);
    cudaGetSymbolAddress((void**)&h1,   g_h1);
    cudaGetSymbolAddress((void**)&h2,   g_h2);
    cudaGetSymbolAddress((void**)&mbuf, g_m);
    cudaGetSymbolAddress((void**)&abuf, g_a);

    const size_t WSZ = 1024u * 1024u;

    cudaFuncSetAttribute((const void*)gemm_f16_kernel<ACT_TANH, __half>,
                         cudaFuncAttributeMaxDynamicSharedMemorySize, GEMM_SMEM);
    cudaFuncSetAttribute((const void*)gemm_f16_kernel<ACT_RELU, __half>,
                         cudaFuncAttributeMaxDynamicSharedMemorySize, GEMM_SMEM);
    cudaFuncSetAttribute((const void*)gemm_f16_kernel<ACT_NONE, float>,
                         cudaFuncAttributeMaxDynamicSharedMemorySize, GEMM_SMEM);

    prep_weights6<<<1024, 256>>>(s_w1, s_w2, s_w3, t_w1, t_w2, t_w3,
                                 mask_in, mask_hid, mask_out, wm);
    prep_x_kernel<<<4096, 256>>>(x, x16);

    dim3 grid(DIM / 128, BATCH / 128);   // (8, 32) = 256 CTAs, 2/SM
    // s branch (tanh)
    gemm_f16_kernel<ACT_TANH, __half><<<grid, 256, GEMM_SMEM>>>(x16, wm + 0 * WSZ, s_b1, h1);
    gemm_f16_kernel<ACT_TANH, __half><<<grid, 256, GEMM_SMEM>>>(h1,  wm + 1 * WSZ, s_b2, h2);
    gemm_f16_kernel<ACT_NONE, float ><<<grid, 256, GEMM_SMEM>>>(h2,  wm + 2 * WSZ, s_b3, mbuf);
    // t branch (relu)
    gemm_f16_kernel<ACT_RELU, __half><<<grid, 256, GEMM_SMEM>>>(x16, wm + 3 * WSZ, t_b1, h1);
    gemm_f16_kernel<ACT_RELU, __half><<<grid, 256, GEMM_SMEM>>>(h1,  wm + 4 * WSZ, t_b2, h2);
    gemm_f16_kernel<ACT_NONE, float ><<<grid, 256, GEMM_SMEM>>>(h2,  wm + 5 * WSZ, t_b3, abuf);

    final_kernel<<<BATCH, 256>>>(x, mbuf, abuf, out);
}

// round 6
// speedup vs baseline: 2.0360x; 1.0088x over previous
#include <cuda_runtime.h>
#include <cuda_fp16.h>
#include <cstdint>
#include <cstddef>

#define BATCH 4096
#define DIM   1024

// ---------------- scratch (static device memory) ----------------------------
__device__ __half g_wm16[6u * 1024u * 1024u];  // fp16 masked weights
__device__ __half g_x16 [BATCH * DIM];         // fp16 input copy
__device__ __half g_h1  [BATCH * DIM];
__device__ __half g_h2  [BATCH * DIM];
__device__ float  g_m   [BATCH * DIM];
__device__ float  g_a   [BATCH * DIM];

// ---------------- helpers ---------------------------------------------------
__device__ __forceinline__ uint32_t smem_u32(const void* p) {
    uint32_t a;
    asm("{ .reg .u64 t; cvta.to.shared.u64 t, %1; cvt.u32.u64 %0, t; }" : "=r"(a) : "l"(p));
    return a;
}

__device__ __forceinline__ void ldm_x4(uint32_t& r0, uint32_t& r1, uint32_t& r2, uint32_t& r3,
                                       uint32_t addr) {
    asm volatile("ldmatrix.sync.aligned.m8n8.x4.shared.b16 {%0,%1,%2,%3}, [%4];"
                 : "=r"(r0), "=r"(r1), "=r"(r2), "=r"(r3) : "r"(addr));
}

__device__ __forceinline__ void mma_f16(float& d0, float& d1, float& d2, float& d3,
                                        uint32_t a0, uint32_t a1, uint32_t a2, uint32_t a3,
                                        uint32_t b0, uint32_t b1) {
    asm("mma.sync.aligned.m16n8k16.row.col.f32.f16.f16.f32 "
        "{%0,%1,%2,%3},{%4,%5,%6,%7},{%8,%9},{%0,%1,%2,%3};\n"
        : "+f"(d0), "+f"(d1), "+f"(d2), "+f"(d3)
        : "r"(a0), "r"(a1), "r"(a2), "r"(a3), "r"(b0), "r"(b1));
}

#define CP_ASYNC16(dst, src) \
    asm volatile("cp.async.cg.shared.global [%0], [%1], 16;" :: "r"(dst), "l"(src) : "memory")
#define CP_COMMIT() asm volatile("cp.async.commit_group;" ::: "memory")
#define CP_WAIT1()  asm volatile("cp.async.wait_group 1;" ::: "memory")

// ---------------- prep kernels ----------------------------------------------
__global__ void prep_weights6(const float* __restrict__ sw1, const float* __restrict__ sw2,
                              const float* __restrict__ sw3, const float* __restrict__ tw1,
                              const float* __restrict__ tw2, const float* __restrict__ tw3,
                              const float* __restrict__ m1, const float* __restrict__ m2,
                              const float* __restrict__ m3, __half* __restrict__ dst) {
    const size_t WSZ = 1024u * 1024u;
    int i = blockIdx.x * blockDim.x + threadIdx.x;   // over 262144 float4
    float4 a1 = reinterpret_cast<const float4*>(m1)[i];
    float4 a2 = reinterpret_cast<const float4*>(m2)[i];
    float4 a3 = reinterpret_cast<const float4*>(m3)[i];
#define DO_W(wp, mk, slot) { \
        float4 wv = reinterpret_cast<const float4*>(wp)[i]; \
        __half2* d2 = reinterpret_cast<__half2*>(dst + (slot) * WSZ); \
        d2[2 * i]     = __floats2half2_rn(wv.x * mk.x, wv.y * mk.y); \
        d2[2 * i + 1] = __floats2half2_rn(wv.z * mk.z, wv.w * mk.w); }
    DO_W(sw1, a1, 0); DO_W(sw2, a2, 1); DO_W(sw3, a3, 2);
    DO_W(tw1, a1, 3); DO_W(tw2, a2, 4); DO_W(tw3, a3, 5);
#undef DO_W
}

__global__ void prep_x_kernel(const float* __restrict__ x, __half* __restrict__ dst) {
    int i = blockIdx.x * blockDim.x + threadIdx.x;
    float4 v = reinterpret_cast<const float4*>(x)[i];
    __half2* d2 = reinterpret_cast<__half2*>(dst);
    d2[2 * i]     = __floats2half2_rn(v.x, v.y);
    d2[2 * i + 1] = __floats2half2_rn(v.z, v.w);
}

// ---------------- GEMM: C = act(A @ W^T + bias), triangular-mask aware ------
// fp16 in, fp32 acc. CTA tile 128x128, BK=64 halves, 256 threads = 8 warps
// (2 x 4), warp tile 64x32. 3-stage cp.async pipeline; rows padded to 144B.
// MADE masks make W ~lower-triangular: for output block [cb, cb+128) only
// K-chunks kt < cb/64+2 are nonzero. The %1023-wrapped masks (layers 2,3)
// additionally keep the LAST chunk (contains the degree-0 column i=1023).
// Skipped chunks contain exact zeros -> results are bit-identical.
#define ACT_TANH 0
#define ACT_RELU 1
#define ACT_NONE 2

#define NCH 16                        // K / BK = 1024 / 64
#define STAGES 3
#define ROWB 144                      // bytes per padded smem row
#define STAGE_BYTES (256 * ROWB)      // 36864
#define B_SMEM_OFF  (128 * ROWB)      // 18432
#define GEMM_SMEM   (STAGES * STAGE_BYTES)   // 110592

template <int ACT, typename OutT, bool ADDLAST>
__global__ __launch_bounds__(256, 2)
void gemm_f16_kernel(const __half* __restrict__ A, const __half* __restrict__ W,
                     const float* __restrict__ bias, OutT* __restrict__ C) {
    extern __shared__ __align__(16) char smc[];
    const uint32_t sbase = smem_u32(smc);

    const int tid   = threadIdx.x;
    const int warp  = tid >> 5;
    const int lane  = tid & 31;
    const int warpM = warp >> 2;         // 0..1 -> 64 rows
    const int warpN = warp & 3;          // 0..3 -> 32 cols
    const int qr    = lane >> 2;         // 0..7
    const int qc    = lane & 3;          // 0..3

    const int rowA0 = blockIdx.y * 128;
    const int colB0 = blockIdx.x * 128;

    // ---- active K-chunk schedule (triangular mask skipping) ----
    const int Klim = min(NCH, (int)blockIdx.x * 2 + 2);      // contiguous chunks [0, Klim)
    const int NACT = (ADDLAST && Klim < NCH) ? Klim + 1 : Klim;
#define CHUNK_OF(j) (((j) < Klim) ? (j) : (NCH - 1))

    float acc[4][4][4];
#pragma unroll
    for (int mf = 0; mf < 4; ++mf)
#pragma unroll
        for (int nf = 0; nf < 4; ++nf)
#pragma unroll
            for (int r = 0; r < 4; ++r) acc[mf][nf][r] = 0.f;

    // ---- cp.async slot bases: 256 threads, 4 A slots + 4 B slots each ----
    const int r0 = tid >> 3;             // 0..31
    const int c  = tid & 7;              // 16B column within 128B row
    const __half* gA = A + (size_t)(rowA0 + r0) * DIM + c * 8;
    const __half* gB = W + (size_t)(colB0 + r0) * DIM + c * 8;
    const uint32_t sA = (uint32_t)(r0 * ROWB + c * 16);
    const uint32_t sB = (uint32_t)(B_SMEM_OFF + r0 * ROWB + c * 16);

#define LOAD_CHUNK(kt, st) do {                                              \
        uint32_t _b = sbase + (uint32_t)(st) * STAGE_BYTES;                  \
        const __half* _ga = gA + (kt) * 64;                                  \
        const __half* _gb = gB + (kt) * 64;                                  \
        _Pragma("unroll")                                                    \
        for (int _i = 0; _i < 4; ++_i) {                                     \
            CP_ASYNC16(_b + sA + _i * (32 * ROWB), _ga + _i * (32 * DIM));   \
            CP_ASYNC16(_b + sB + _i * (32 * ROWB), _gb + _i * (32 * DIM));   \
        }                                                                    \
    } while (0)

    // ---- ldmatrix per-thread base offsets ----
    uint32_t aoff[4], boff[2];
#pragma unroll
    for (int mf = 0; mf < 4; ++mf) {
        int arow = warpM * 64 + mf * 16 + (lane & 15);
        aoff[mf] = (uint32_t)(arow * ROWB + ((lane >> 4) & 1) * 16);
    }
#pragma unroll
    for (int np = 0; np < 2; ++np) {
        int brow = warpN * 32 + np * 16 + (lane & 7) + ((lane >> 4) & 1) * 8;
        boff[np] = (uint32_t)(B_SMEM_OFF + brow * ROWB + ((lane >> 3) & 1) * 16);
    }

    // Prologue: prefetch active chunks 0 and 1 (Klim >= 2 always)
    LOAD_CHUNK(CHUNK_OF(0), 0); CP_COMMIT();
    LOAD_CHUNK(CHUNK_OF(1), 1); CP_COMMIT();

    int st_c = 0;
    for (int j = 0; j < NACT; ++j) {
        CP_WAIT1();
        __syncthreads();

        if (j + 2 < NACT) {
            int st_n = st_c + 2; if (st_n >= STAGES) st_n -= STAGES;
            LOAD_CHUNK(CHUNK_OF(j + 2), st_n);
        }
        CP_COMMIT();

        const uint32_t stb = sbase + (uint32_t)st_c * STAGE_BYTES;
#pragma unroll
        for (int s = 0; s < 4; ++s) {        // k16 steps within the 64-chunk
            uint32_t afr[4][4];
            uint32_t bfr[4][2];
#pragma unroll
            for (int mf = 0; mf < 4; ++mf)
                ldm_x4(afr[mf][0], afr[mf][1], afr[mf][2], afr[mf][3],
                       stb + aoff[mf] + s * 32);
#pragma unroll
            for (int np = 0; np < 2; ++np)
                ldm_x4(bfr[2 * np][0], bfr[2 * np][1],
                       bfr[2 * np + 1][0], bfr[2 * np + 1][1],
                       stb + boff[np] + s * 32);
#pragma unroll
            for (int mf = 0; mf < 4; ++mf)
#pragma unroll
                for (int nf = 0; nf < 4; ++nf)
                    mma_f16(acc[mf][nf][0], acc[mf][nf][1], acc[mf][nf][2], acc[mf][nf][3],
                            afr[mf][0], afr[mf][1], afr[mf][2], afr[mf][3],
                            bfr[nf][0], bfr[nf][1]);
        }
        ++st_c; if (st_c >= STAGES) st_c = 0;
    }
#undef CHUNK_OF
#undef LOAD_CHUNK

    // ---- epilogue: bias + activation; fp16 store for intermediates ----
#pragma unroll
    for (int mf = 0; mf < 4; ++mf) {
#pragma unroll
        for (int nf = 0; nf < 4; ++nf) {
            int row0 = rowA0 + warpM * 64 + mf * 16 + qr;
            int col0 = colB0 + warpN * 32 + nf * 8 + 2 * qc;
            float b0 = bias[col0];
            float b1 = bias[col0 + 1];
            float v0 = acc[mf][nf][0] + b0;
            float v1 = acc[mf][nf][1] + b1;
            float v2 = acc[mf][nf][2] + b0;
            float v3 = acc[mf][nf][3] + b1;
            if (ACT == ACT_TANH) {
                v0 = tanhf(v0); v1 = tanhf(v1); v2 = tanhf(v2); v3 = tanhf(v3);
            } else if (ACT == ACT_RELU) {
                v0 = fmaxf(v0, 0.f); v1 = fmaxf(v1, 0.f);
                v2 = fmaxf(v2, 0.f); v3 = fmaxf(v3, 0.f);
            }
            if (sizeof(OutT) == 2) {   // __half intermediate
                __half2* p0 = reinterpret_cast<__half2*>((__half*)C + (size_t)row0 * DIM + col0);
                __half2* p1 = reinterpret_cast<__half2*>((__half*)C + (size_t)(row0 + 8) * DIM + col0);
                *p0 = __floats2half2_rn(v0, v1);
                *p1 = __floats2half2_rn(v2, v3);
            } else {                    // float output (m / a)
                *reinterpret_cast<float2*>((float*)C + (size_t)row0 * DIM + col0)       = make_float2(v0, v1);
                *reinterpret_cast<float2*>((float*)C + (size_t)(row0 + 8) * DIM + col0) = make_float2(v2, v3);
            }
        }
    }
}

// ---------------- final elementwise + logdet --------------------------------
__global__ void final_kernel(const float* __restrict__ x, const float* __restrict__ m,
                             const float* __restrict__ a, float* __restrict__ out) {
    int b = blockIdx.x;
    int t = threadIdx.x;
    size_t base = (size_t)b * DIM;
    float s = 0.f;
#pragma unroll
    for (int i = 0; i < 4; ++i) {
        int c = t + i * 256;
        float av = a[base + c];
        float mv = m[base + c];
        float xv = x[base + c];
        out[base + c] = (xv - mv) * expf(-av);
        s += av;
    }
#pragma unroll
    for (int o = 16; o; o >>= 1) s += __shfl_down_sync(0xFFFFFFFFu, s, o);
    __shared__ float ws[8];
    if ((t & 31) == 0) ws[t >> 5] = s;
    __syncthreads();
    if (t < 8) {
        float v = ws[t];
#pragma unroll
        for (int o = 4; o; o >>= 1) v += __shfl_down_sync(0xFFu, v, o);
        if (t == 0) out[(size_t)BATCH * DIM + b] = -v;
    }
}

// ---------------- launcher ---------------------------------------------------
extern "C" void kernel_launch(void* const* d_in, const int* in_sizes, int n_in,
                              void* d_out, int out_size) {
    (void)in_sizes; (void)n_in; (void)out_size;
    const float* x      = (const float*)d_in[0];
    const float* s_w1   = (const float*)d_in[1];
    const float* s_b1   = (const float*)d_in[2];
    const float* s_w2   = (const float*)d_in[3];
    const float* s_b2   = (const float*)d_in[4];
    const float* s_w3   = (const float*)d_in[5];
    const float* s_b3   = (const float*)d_in[6];
    const float* t_w1   = (const float*)d_in[7];
    const float* t_b1   = (const float*)d_in[8];
    const float* t_w2   = (const float*)d_in[9];
    const float* t_b2   = (const float*)d_in[10];
    const float* t_w3   = (const float*)d_in[11];
    const float* t_b3   = (const float*)d_in[12];
    const float* mask_in  = (const float*)d_in[13];
    const float* mask_hid = (const float*)d_in[14];
    const float* mask_out = (const float*)d_in[15];
    float* out = (float*)d_out;

    __half *wm, *x16, *h1, *h2;
    float *mbuf, *abuf;
    cudaGetSymbolAddress((void**)&wm,   g_wm16);
    cudaGetSymbolAddress((void**)&x16,  g_x16);
    cudaGetSymbolAddress((void**)&h1,   g_h1);
    cudaGetSymbolAddress((void**)&h2,   g_h2);
    cudaGetSymbolAddress((void**)&mbuf, g_m);
    cudaGetSymbolAddress((void**)&abuf, g_a);

    const size_t WSZ = 1024u * 1024u;

    cudaFuncSetAttribute((const void*)gemm_f16_kernel<ACT_TANH, __half, false>,
                         cudaFuncAttributeMaxDynamicSharedMemorySize, GEMM_SMEM);
    cudaFuncSetAttribute((const void*)gemm_f16_kernel<ACT_RELU, __half, false>,
                         cudaFuncAttributeMaxDynamicSharedMemorySize, GEMM_SMEM);
    cudaFuncSetAttribute((const void*)gemm_f16_kernel<ACT_TANH, __half, true>,
                         cudaFuncAttributeMaxDynamicSharedMemorySize, GEMM_SMEM);
    cudaFuncSetAttribute((const void*)gemm_f16_kernel<ACT_RELU, __half, true>,
                         cudaFuncAttributeMaxDynamicSharedMemorySize, GEMM_SMEM);
    cudaFuncSetAttribute((const void*)gemm_f16_kernel<ACT_NONE, float, true>,
                         cudaFuncAttributeMaxDynamicSharedMemorySize, GEMM_SMEM);

    prep_weights6<<<1024, 256>>>(s_w1, s_w2, s_w3, t_w1, t_w2, t_w3,
                                 mask_in, mask_hid, mask_out, wm);
    prep_x_kernel<<<4096, 256>>>(x, x16);

    dim3 grid(DIM / 128, BATCH / 128);   // (8, 32) = 256 CTAs, 2/SM
    // s branch (tanh); layer1 uses mask_in (no wrap col), layers 2/3 keep last chunk
    gemm_f16_kernel<ACT_TANH, __half, false><<<grid, 256, GEMM_SMEM>>>(x16, wm + 0 * WSZ, s_b1, h1);
    gemm_f16_kernel<ACT_TANH, __half, true ><<<grid, 256, GEMM_SMEM>>>(h1,  wm + 1 * WSZ, s_b2, h2);
    gemm_f16_kernel<ACT_NONE, float,  true ><<<grid, 256, GEMM_SMEM>>>(h2,  wm + 2 * WSZ, s_b3, mbuf);
    // t branch (relu)
    gemm_f16_kernel<ACT_RELU, __half, false><<<grid, 256, GEMM_SMEM>>>(x16, wm + 3 * WSZ, t_b1, h1);
    gemm_f16_kernel<ACT_RELU, __half, true ><<<grid, 256, GEMM_SMEM>>>(h1,  wm + 4 * WSZ, t_b2, h2);
    gemm_f16_kernel<ACT_NONE, float,  true ><<<grid, 256, GEMM_SMEM>>>(h2,  wm + 5 * WSZ, t_b3, abuf);

    final_kernel<<<BATCH, 256>>>(x, mbuf, abuf, out);
}

// round 7
// speedup vs baseline: 2.5336x; 1.2444x over previous
#include <cuda_runtime.h>
#include <cuda_fp16.h>
#include <cstdint>
#include <cstddef>

#define BATCH 4096
#define DIM   1024

// ---------------- scratch (static device memory) ----------------------------
__device__ __half g_wm16[6u * 1024u * 1024u];  // fp16 masked weights
__device__ __half g_x16 [BATCH * DIM];         // fp16 input copy
__device__ __half g_h1  [BATCH * DIM];
__device__ __half g_h2  [BATCH * DIM];
__device__ float  g_m   [BATCH * DIM];
__device__ float  g_a   [BATCH * DIM];

// ---------------- helpers ---------------------------------------------------
__device__ __forceinline__ uint32_t smem_u32(const void* p) {
    uint32_t a;
    asm("{ .reg .u64 t; cvta.to.shared.u64 t, %1; cvt.u32.u64 %0, t; }" : "=r"(a) : "l"(p));
    return a;
}

__device__ __forceinline__ void ldm_x4(uint32_t& r0, uint32_t& r1, uint32_t& r2, uint32_t& r3,
                                       uint32_t addr) {
    asm volatile("ldmatrix.sync.aligned.m8n8.x4.shared.b16 {%0,%1,%2,%3}, [%4];"
                 : "=r"(r0), "=r"(r1), "=r"(r2), "=r"(r3) : "r"(addr));
}

__device__ __forceinline__ void mma_f16(float& d0, float& d1, float& d2, float& d3,
                                        uint32_t a0, uint32_t a1, uint32_t a2, uint32_t a3,
                                        uint32_t b0, uint32_t b1) {
    asm("mma.sync.aligned.m16n8k16.row.col.f32.f16.f16.f32 "
        "{%0,%1,%2,%3},{%4,%5,%6,%7},{%8,%9},{%0,%1,%2,%3};\n"
        : "+f"(d0), "+f"(d1), "+f"(d2), "+f"(d3)
        : "r"(a0), "r"(a1), "r"(a2), "r"(a3), "r"(b0), "r"(b1));
}

#define CP_ASYNC16(dst, src) \
    asm volatile("cp.async.cg.shared.global [%0], [%1], 16;" :: "r"(dst), "l"(src) : "memory")
#define CP_COMMIT() asm volatile("cp.async.commit_group;" ::: "memory")
#define CP_WAIT2()  asm volatile("cp.async.wait_group 2;" ::: "memory")

// ---------------- prep kernels ----------------------------------------------
__global__ void prep_weights6(const float* __restrict__ sw1, const float* __restrict__ sw2,
                              const float* __restrict__ sw3, const float* __restrict__ tw1,
                              const float* __restrict__ tw2, const float* __restrict__ tw3,
                              const float* __restrict__ m1, const float* __restrict__ m2,
                              const float* __restrict__ m3, __half* __restrict__ dst) {
    const size_t WSZ = 1024u * 1024u;
    int i = blockIdx.x * blockDim.x + threadIdx.x;   // over 262144 float4
    float4 a1 = reinterpret_cast<const float4*>(m1)[i];
    float4 a2 = reinterpret_cast<const float4*>(m2)[i];
    float4 a3 = reinterpret_cast<const float4*>(m3)[i];
#define DO_W(wp, mk, slot) { \
        float4 wv = reinterpret_cast<const float4*>(wp)[i]; \
        __half2* d2 = reinterpret_cast<__half2*>(dst + (slot) * WSZ); \
        d2[2 * i]     = __floats2half2_rn(wv.x * mk.x, wv.y * mk.y); \
        d2[2 * i + 1] = __floats2half2_rn(wv.z * mk.z, wv.w * mk.w); }
    DO_W(sw1, a1, 0); DO_W(sw2, a2, 1); DO_W(sw3, a3, 2);
    DO_W(tw1, a1, 3); DO_W(tw2, a2, 4); DO_W(tw3, a3, 5);
#undef DO_W
}

__global__ void prep_x_kernel(const float* __restrict__ x, __half* __restrict__ dst) {
    int i = blockIdx.x * blockDim.x + threadIdx.x;
    float4 v = reinterpret_cast<const float4*>(x)[i];
    __half2* d2 = reinterpret_cast<__half2*>(dst);
    d2[2 * i]     = __floats2half2_rn(v.x, v.y);
    d2[2 * i + 1] = __floats2half2_rn(v.z, v.w);
}

// ---------------- GEMM: C = act(A @ W^T + bias), mask-aware + balanced -------
// fp16 in, fp32 acc. CTA M-tile 128, BK=64 halves, 256 threads = 8 warps
// (2 x 4), warp tile 64x32. 4-stage cp.async pipeline, prefetch distance 3.
// Work balancing: column block cb has only chunks [0, 2cb+2) nonzero (plus the
// wrap chunk 15 for %1023 masks). Each CTA processes the complementary pair
// (7-p, p) -> exactly 18(+wrap) chunks per CTA, perfectly flat across the grid.
#define ACT_TANH 0
#define ACT_RELU 1
#define ACT_NONE 2

#define NCH 16                        // K / BK = 1024 / 64
#define STAGES 4
#define ROWB 144                      // bytes per padded smem row
#define STAGE_BYTES (256 * ROWB)      // 36864
#define B_SMEM_OFF  (128 * ROWB)      // 18432
#define GEMM_SMEM   (STAGES * STAGE_BYTES)   // 147456

template <int ACT, typename OutT, bool ADDLAST>
__global__ __launch_bounds__(256, 1)
void gemm_f16_kernel(const __half* __restrict__ A, const __half* __restrict__ W,
                     const float* __restrict__ bias, OutT* __restrict__ C) {
    extern __shared__ __align__(16) char smc[];
    const uint32_t sbase = smem_u32(smc);

    const int tid   = threadIdx.x;
    const int warp  = tid >> 5;
    const int lane  = tid & 31;
    const int warpM = warp >> 2;         // 0..1 -> 64 rows
    const int warpN = warp & 3;          // 0..3 -> 32 cols
    const int qr    = lane >> 2;         // 0..7
    const int qc    = lane & 3;          // 0..3

    const int rowA0 = blockIdx.y * 128;
    const int p     = blockIdx.x;        // 0..3

    // ---- cp.async slot bases: 256 threads, 4 A slots + 4 B slots each ----
    const int r0 = tid >> 3;             // 0..31
    const int c  = tid & 7;              // 16B column within 128B row
    const __half* gA = A + (size_t)(rowA0 + r0) * DIM + c * 8;
    const uint32_t sA = (uint32_t)(r0 * ROWB + c * 16);
    const uint32_t sB = (uint32_t)(B_SMEM_OFF + r0 * ROWB + c * 16);

    // ---- ldmatrix per-thread base offsets (pass-invariant) ----
    uint32_t aoff[4], boff[2];
#pragma unroll
    for (int mf = 0; mf < 4; ++mf) {
        int arow = warpM * 64 + mf * 16 + (lane & 15);
        aoff[mf] = (uint32_t)(arow * ROWB + ((lane >> 4) & 1) * 16);
    }
#pragma unroll
    for (int np = 0; np < 2; ++np) {
        int brow = warpN * 32 + np * 16 + (lane & 7) + ((lane >> 4) & 1) * 8;
        boff[np] = (uint32_t)(B_SMEM_OFF + brow * ROWB + ((lane >> 3) & 1) * 16);
    }

    for (int pass = 0; pass < 2; ++pass) {
        const int cb    = (pass == 0) ? (7 - p) : p;   // heavy block first
        const int colB0 = cb * 128;
        const int Klim  = min(NCH, cb * 2 + 2);
        const int NACT  = (ADDLAST && Klim < NCH) ? Klim + 1 : Klim;
#define CHUNK_OF(j) (((j) < Klim) ? (j) : (NCH - 1))

        const __half* gB = W + (size_t)(colB0 + r0) * DIM + c * 8;

        float acc[4][4][4];
#pragma unroll
        for (int mf = 0; mf < 4; ++mf)
#pragma unroll
            for (int nf = 0; nf < 4; ++nf)
#pragma unroll
                for (int r = 0; r < 4; ++r) acc[mf][nf][r] = 0.f;

#define LOAD_CHUNK(kt, st) do {                                              \
        uint32_t _b = sbase + (uint32_t)(st) * STAGE_BYTES;                  \
        const __half* _ga = gA + (kt) * 64;                                  \
        const __half* _gb = gB + (kt) * 64;                                  \
        _Pragma("unroll")                                                    \
        for (int _i = 0; _i < 4; ++_i) {                                     \
            CP_ASYNC16(_b + sA + _i * (32 * ROWB), _ga + _i * (32 * DIM));   \
            CP_ASYNC16(_b + sB + _i * (32 * ROWB), _gb + _i * (32 * DIM));   \
        }                                                                    \
    } while (0)

        if (pass == 1) __syncthreads();   // stages from pass 0 fully consumed

        // Prologue: prefetch up to 3 active chunks (NACT >= 2 always)
        LOAD_CHUNK(CHUNK_OF(0), 0); CP_COMMIT();
        LOAD_CHUNK(CHUNK_OF(1), 1); CP_COMMIT();
        if (NACT > 2) LOAD_CHUNK(CHUNK_OF(2), 2);
        CP_COMMIT();

        int st_c = 0;
        for (int j = 0; j < NACT; ++j) {
            CP_WAIT2();
            __syncthreads();

            if (j + 3 < NACT) {
                int st_n = st_c + 3; if (st_n >= STAGES) st_n -= STAGES;
                LOAD_CHUNK(CHUNK_OF(j + 3), st_n);
            }
            CP_COMMIT();

            const uint32_t stb = sbase + (uint32_t)st_c * STAGE_BYTES;
#pragma unroll
            for (int s = 0; s < 4; ++s) {        // k16 steps within the 64-chunk
                uint32_t afr[4][4];
                uint32_t bfr[4][2];
#pragma unroll
                for (int mf = 0; mf < 4; ++mf)
                    ldm_x4(afr[mf][0], afr[mf][1], afr[mf][2], afr[mf][3],
                           stb + aoff[mf] + s * 32);
#pragma unroll
                for (int np = 0; np < 2; ++np)
                    ldm_x4(bfr[2 * np][0], bfr[2 * np][1],
                           bfr[2 * np + 1][0], bfr[2 * np + 1][1],
                           stb + boff[np] + s * 32);
#pragma unroll
                for (int mf = 0; mf < 4; ++mf)
#pragma unroll
                    for (int nf = 0; nf < 4; ++nf)
                        mma_f16(acc[mf][nf][0], acc[mf][nf][1], acc[mf][nf][2], acc[mf][nf][3],
                                afr[mf][0], afr[mf][1], afr[mf][2], afr[mf][3],
                                bfr[nf][0], bfr[nf][1]);
            }
            ++st_c; if (st_c >= STAGES) st_c = 0;
        }
#undef CHUNK_OF
#undef LOAD_CHUNK

        // ---- epilogue: bias + activation; fp16 store for intermediates ----
#pragma unroll
        for (int mf = 0; mf < 4; ++mf) {
#pragma unroll
            for (int nf = 0; nf < 4; ++nf) {
                int row0 = rowA0 + warpM * 64 + mf * 16 + qr;
                int col0 = colB0 + warpN * 32 + nf * 8 + 2 * qc;
                float b0 = bias[col0];
                float b1 = bias[col0 + 1];
                float v0 = acc[mf][nf][0] + b0;
                float v1 = acc[mf][nf][1] + b1;
                float v2 = acc[mf][nf][2] + b0;
                float v3 = acc[mf][nf][3] + b1;
                if (ACT == ACT_TANH) {
                    v0 = tanhf(v0); v1 = tanhf(v1); v2 = tanhf(v2); v3 = tanhf(v3);
                } else if (ACT == ACT_RELU) {
                    v0 = fmaxf(v0, 0.f); v1 = fmaxf(v1, 0.f);
                    v2 = fmaxf(v2, 0.f); v3 = fmaxf(v3, 0.f);
                }
                if (sizeof(OutT) == 2) {   // __half intermediate
                    __half2* p0 = reinterpret_cast<__half2*>((__half*)C + (size_t)row0 * DIM + col0);
                    __half2* p1 = reinterpret_cast<__half2*>((__half*)C + (size_t)(row0 + 8) * DIM + col0);
                    *p0 = __floats2half2_rn(v0, v1);
                    *p1 = __floats2half2_rn(v2, v3);
                } else {                    // float output (m / a)
                    *reinterpret_cast<float2*>((float*)C + (size_t)row0 * DIM + col0)       = make_float2(v0, v1);
                    *reinterpret_cast<float2*>((float*)C + (size_t)(row0 + 8) * DIM + col0) = make_float2(v2, v3);
                }
            }
        }
    }
}

// ---------------- final elementwise + logdet --------------------------------
__global__ void final_kernel(const float* __restrict__ x, const float* __restrict__ m,
                             const float* __restrict__ a, float* __restrict__ out) {
    int b = blockIdx.x;
    int t = threadIdx.x;
    size_t base = (size_t)b * DIM;
    float s = 0.f;
#pragma unroll
    for (int i = 0; i < 4; ++i) {
        int c = t + i * 256;
        float av = a[base + c];
        float mv = m[base + c];
        float xv = x[base + c];
        out[base + c] = (xv - mv) * expf(-av);
        s += av;
    }
#pragma unroll
    for (int o = 16; o; o >>= 1) s += __shfl_down_sync(0xFFFFFFFFu, s, o);
    __shared__ float ws[8];
    if ((t & 31) == 0) ws[t >> 5] = s;
    __syncthreads();
    if (t < 8) {
        float v = ws[t];
#pragma unroll
        for (int o = 4; o; o >>= 1) v += __shfl_down_sync(0xFFu, v, o);
        if (t == 0) out[(size_t)BATCH * DIM + b] = -v;
    }
}

// ---------------- launcher ---------------------------------------------------
extern "C" void kernel_launch(void* const* d_in, const int* in_sizes, int n_in,
                              void* d_out, int out_size) {
    (void)in_sizes; (void)n_in; (void)out_size;
    const float* x      = (const float*)d_in[0];
    const float* s_w1   = (const float*)d_in[1];
    const float* s_b1   = (const float*)d_in[2];
    const float* s_w2   = (const float*)d_in[3];
    const float* s_b2   = (const float*)d_in[4];
    const float* s_w3   = (const float*)d_in[5];
    const float* s_b3   = (const float*)d_in[6];
    const float* t_w1   = (const float*)d_in[7];
    const float* t_b1   = (const float*)d_in[8];
    const float* t_w2   = (const float*)d_in[9];
    const float* t_b2   = (const float*)d_in[10];
    const float* t_w3   = (const float*)d_in[11];
    const float* t_b3   = (const float*)d_in[12];
    const float* mask_in  = (const float*)d_in[13];
    const float* mask_hid = (const float*)d_in[14];
    const float* mask_out = (const float*)d_in[15];
    float* out = (float*)d_out;

    __half *wm, *x16, *h1, *h2;
    float *mbuf, *abuf;
    cudaGetSymbolAddress((void**)&wm,   g_wm16);
    cudaGetSymbolAddress((void**)&x16,  g_x16);
    cudaGetSymbolAddress((void**)&h1,   g_h1);
    cudaGetSymbolAddress((void**)&h2,   g_h2);
    cudaGetSymbolAddress((void**)&mbuf, g_m);
    cudaGetSymbolAddress((void**)&abuf, g_a);

    const size_t WSZ = 1024u * 1024u;

    cudaFuncSetAttribute((const void*)gemm_f16_kernel<ACT_TANH, __half, false>,
                         cudaFuncAttributeMaxDynamicSharedMemorySize, GEMM_SMEM);
    cudaFuncSetAttribute((const void*)gemm_f16_kernel<ACT_RELU, __half, false>,
                         cudaFuncAttributeMaxDynamicSharedMemorySize, GEMM_SMEM);
    cudaFuncSetAttribute((const void*)gemm_f16_kernel<ACT_TANH, __half, true>,
                         cudaFuncAttributeMaxDynamicSharedMemorySize, GEMM_SMEM);
    cudaFuncSetAttribute((const void*)gemm_f16_kernel<ACT_RELU, __half, true>,
                         cudaFuncAttributeMaxDynamicSharedMemorySize, GEMM_SMEM);
    cudaFuncSetAttribute((const void*)gemm_f16_kernel<ACT_NONE, float, true>,
                         cudaFuncAttributeMaxDynamicSharedMemorySize, GEMM_SMEM);

    prep_weights6<<<1024, 256>>>(s_w1, s_w2, s_w3, t_w1, t_w2, t_w3,
                                 mask_in, mask_hid, mask_out, wm);
    prep_x_kernel<<<4096, 256>>>(x, x16);

    dim3 grid(4, BATCH / 128);   // (4, 32) = 128 CTAs, balanced pairs, 1 wave
    // s branch (tanh); layer1 uses mask_in (no wrap col), layers 2/3 keep last chunk
    gemm_f16_kernel<ACT_TANH, __half, false><<<grid, 256, GEMM_SMEM>>>(x16, wm + 0 * WSZ, s_b1, h1);
    gemm_f16_kernel<ACT_TANH, __half, true ><<<grid, 256, GEMM_SMEM>>>(h1,  wm + 1 * WSZ, s_b2, h2);
    gemm_f16_kernel<ACT_NONE, float,  true ><<<grid, 256, GEMM_SMEM>>>(h2,  wm + 2 * WSZ, s_b3, mbuf);
    // t branch (relu)
    gemm_f16_kernel<ACT_RELU, __half, false><<<grid, 256, GEMM_SMEM>>>(x16, wm + 3 * WSZ, t_b1, h1);
    gemm_f16_kernel<ACT_RELU, __half, true ><<<grid, 256, GEMM_SMEM>>>(h1,  wm + 4 * WSZ, t_b2, h2);
    gemm_f16_kernel<ACT_NONE, float,  true ><<<grid, 256, GEMM_SMEM>>>(h2,  wm + 5 * WSZ, t_b3, abuf);

    final_kernel<<<BATCH, 256>>>(x, mbuf, abuf, out);
}

// round 8
// speedup vs baseline: 2.5652x; 1.0125x over previous
#include <cuda_runtime.h>
#include <cuda_fp16.h>
#include <cstdint>
#include <cstddef>

#define BATCH 4096
#define DIM   1024

// ---------------- scratch (static device memory) ----------------------------
__device__ __half g_wm16[6u * 1024u * 1024u];  // fp16 masked weights
__device__ __half g_x16 [BATCH * DIM];         // fp16 input copy
__device__ __half g_h1s [BATCH * DIM];
__device__ __half g_h2s [BATCH * DIM];
__device__ __half g_h1t [BATCH * DIM];
__device__ __half g_h2t [BATCH * DIM];
__device__ float  g_m   [BATCH * DIM];
__device__ float  g_a   [BATCH * DIM];

// ---------------- helpers ---------------------------------------------------
__device__ __forceinline__ uint32_t smem_u32(const void* p) {
    uint32_t a;
    asm("{ .reg .u64 t; cvta.to.shared.u64 t, %1; cvt.u32.u64 %0, t; }" : "=r"(a) : "l"(p));
    return a;
}

__device__ __forceinline__ void ldm_x4(uint32_t& r0, uint32_t& r1, uint32_t& r2, uint32_t& r3,
                                       uint32_t addr) {
    asm volatile("ldmatrix.sync.aligned.m8n8.x4.shared.b16 {%0,%1,%2,%3}, [%4];"
                 : "=r"(r0), "=r"(r1), "=r"(r2), "=r"(r3) : "r"(addr));
}

__device__ __forceinline__ void mma_f16(float& d0, float& d1, float& d2, float& d3,
                                        uint32_t a0, uint32_t a1, uint32_t a2, uint32_t a3,
                                        uint32_t b0, uint32_t b1) {
    asm("mma.sync.aligned.m16n8k16.row.col.f32.f16.f16.f32 "
        "{%0,%1,%2,%3},{%4,%5,%6,%7},{%8,%9},{%0,%1,%2,%3};\n"
        : "+f"(d0), "+f"(d1), "+f"(d2), "+f"(d3)
        : "r"(a0), "r"(a1), "r"(a2), "r"(a3), "r"(b0), "r"(b1));
}

#define CP_ASYNC16(dst, src) \
    asm volatile("cp.async.cg.shared.global [%0], [%1], 16;" :: "r"(dst), "l"(src) : "memory")
#define CP_COMMIT() asm volatile("cp.async.commit_group;" ::: "memory")
#define CP_WAIT1()  asm volatile("cp.async.wait_group 1;" ::: "memory")

// ---------------- prep kernels ----------------------------------------------
__global__ void prep_weights6(const float* __restrict__ sw1, const float* __restrict__ sw2,
                              const float* __restrict__ sw3, const float* __restrict__ tw1,
                              const float* __restrict__ tw2, const float* __restrict__ tw3,
                              const float* __restrict__ m1, const float* __restrict__ m2,
                              const float* __restrict__ m3, __half* __restrict__ dst) {
    const size_t WSZ = 1024u * 1024u;
    int i = blockIdx.x * blockDim.x + threadIdx.x;   // over 262144 float4
    float4 a1 = reinterpret_cast<const float4*>(m1)[i];
    float4 a2 = reinterpret_cast<const float4*>(m2)[i];
    float4 a3 = reinterpret_cast<const float4*>(m3)[i];
#define DO_W(wp, mk, slot) { \
        float4 wv = reinterpret_cast<const float4*>(wp)[i]; \
        __half2* d2 = reinterpret_cast<__half2*>(dst + (slot) * WSZ); \
        d2[2 * i]     = __floats2half2_rn(wv.x * mk.x, wv.y * mk.y); \
        d2[2 * i + 1] = __floats2half2_rn(wv.z * mk.z, wv.w * mk.w); }
    DO_W(sw1, a1, 0); DO_W(sw2, a2, 1); DO_W(sw3, a3, 2);
    DO_W(tw1, a1, 3); DO_W(tw2, a2, 4); DO_W(tw3, a3, 5);
#undef DO_W
}

__global__ void prep_x_kernel(const float* __restrict__ x, __half* __restrict__ dst) {
    int i = blockIdx.x * blockDim.x + threadIdx.x;
    float4 v = reinterpret_cast<const float4*>(x)[i];
    __half2* d2 = reinterpret_cast<__half2*>(dst);
    d2[2 * i]     = __floats2half2_rn(v.x, v.y);
    d2[2 * i + 1] = __floats2half2_rn(v.z, v.w);
}

// ---------------- fused dual-branch GEMM ------------------------------------
// z = blockIdx.z selects branch (s: z=0, t: z=1) -> own A, W, bias, C, act.
// fp16 in, fp32 acc. CTA tile 128x128, BK=64, 256 threads = 8 warps (2x4),
// warp tile 64x32. 3-stage cp.async pipeline (110 KB smem -> 2 CTAs/SM).
// Mask-aware K-skipping: column block cb only needs chunks [0, 2cb+2)
// (+ wrap chunk 15 for %1023 masks). Heavy blocks scheduled first (cb = 7-bx).
#define ACT_TANH 0
#define ACT_RELU 1
#define ACT_NONE 2

#define NCH 16                        // K / BK = 1024 / 64
#define STAGES 3
#define ROWB 144                      // bytes per padded smem row
#define STAGE_BYTES (256 * ROWB)      // 36864
#define B_SMEM_OFF  (128 * ROWB)      // 18432
#define GEMM_SMEM   (STAGES * STAGE_BYTES)   // 110592

template <int ACT0, int ACT1, typename OutT, bool ADDLAST>
__global__ __launch_bounds__(256, 2)
void gemm_dual_kernel(const __half* __restrict__ A0, const __half* __restrict__ A1,
                      const __half* __restrict__ W0, const __half* __restrict__ W1,
                      const float* __restrict__ bias0, const float* __restrict__ bias1,
                      OutT* __restrict__ C0, OutT* __restrict__ C1) {
    extern __shared__ __align__(16) char smc[];
    const uint32_t sbase = smem_u32(smc);

    const int z = blockIdx.z;
    const __half* A    = z ? A1 : A0;
    const __half* W    = z ? W1 : W0;
    const float*  bias = z ? bias1 : bias0;
    OutT*         C    = z ? C1 : C0;
    const int     act  = z ? ACT1 : ACT0;

    const int tid   = threadIdx.x;
    const int warp  = tid >> 5;
    const int lane  = tid & 31;
    const int warpM = warp >> 2;         // 0..1 -> 64 rows
    const int warpN = warp & 3;          // 0..3 -> 32 cols
    const int qr    = lane >> 2;         // 0..7
    const int qc    = lane & 3;          // 0..3

    const int rowA0 = blockIdx.y * 128;
    const int cb    = 7 - (int)blockIdx.x;   // heavy column blocks first
    const int colB0 = cb * 128;

    // ---- active K-chunk schedule ----
    const int Klim = min(NCH, cb * 2 + 2);
    const int NACT = (ADDLAST && Klim < NCH) ? Klim + 1 : Klim;
#define CHUNK_OF(j) (((j) < Klim) ? (j) : (NCH - 1))

    float acc[4][4][4];
#pragma unroll
    for (int mf = 0; mf < 4; ++mf)
#pragma unroll
        for (int nf = 0; nf < 4; ++nf)
#pragma unroll
            for (int r = 0; r < 4; ++r) acc[mf][nf][r] = 0.f;

    // ---- cp.async slot bases: 256 threads, 4 A slots + 4 B slots each ----
    const int r0 = tid >> 3;             // 0..31
    const int c  = tid & 7;              // 16B column within 128B row
    const __half* gA = A + (size_t)(rowA0 + r0) * DIM + c * 8;
    const __half* gB = W + (size_t)(colB0 + r0) * DIM + c * 8;
    const uint32_t sA = (uint32_t)(r0 * ROWB + c * 16);
    const uint32_t sB = (uint32_t)(B_SMEM_OFF + r0 * ROWB + c * 16);

#define LOAD_CHUNK(kt, st) do {                                              \
        uint32_t _b = sbase + (uint32_t)(st) * STAGE_BYTES;                  \
        const __half* _ga = gA + (kt) * 64;                                  \
        const __half* _gb = gB + (kt) * 64;                                  \
        _Pragma("unroll")                                                    \
        for (int _i = 0; _i < 4; ++_i) {                                     \
            CP_ASYNC16(_b + sA + _i * (32 * ROWB), _ga + _i * (32 * DIM));   \
            CP_ASYNC16(_b + sB + _i * (32 * ROWB), _gb + _i * (32 * DIM));   \
        }                                                                    \
    } while (0)

    // ---- ldmatrix per-thread base offsets ----
    uint32_t aoff[4], boff[2];
#pragma unroll
    for (int mf = 0; mf < 4; ++mf) {
        int arow = warpM * 64 + mf * 16 + (lane & 15);
        aoff[mf] = (uint32_t)(arow * ROWB + ((lane >> 4) & 1) * 16);
    }
#pragma unroll
    for (int np = 0; np < 2; ++np) {
        int brow = warpN * 32 + np * 16 + (lane & 7) + ((lane >> 4) & 1) * 8;
        boff[np] = (uint32_t)(B_SMEM_OFF + brow * ROWB + ((lane >> 3) & 1) * 16);
    }

    // Prologue: prefetch active chunks 0 and 1 (NACT >= 2 always)
    LOAD_CHUNK(CHUNK_OF(0), 0); CP_COMMIT();
    LOAD_CHUNK(CHUNK_OF(1), 1); CP_COMMIT();

    int st_c = 0;
    for (int j = 0; j < NACT; ++j) {
        CP_WAIT1();
        __syncthreads();

        if (j + 2 < NACT) {
            int st_n = st_c + 2; if (st_n >= STAGES) st_n -= STAGES;
            LOAD_CHUNK(CHUNK_OF(j + 2), st_n);
        }
        CP_COMMIT();

        const uint32_t stb = sbase + (uint32_t)st_c * STAGE_BYTES;
#pragma unroll
        for (int s = 0; s < 4; ++s) {        // k16 steps within the 64-chunk
            uint32_t afr[4][4];
            uint32_t bfr[4][2];
#pragma unroll
            for (int mf = 0; mf < 4; ++mf)
                ldm_x4(afr[mf][0], afr[mf][1], afr[mf][2], afr[mf][3],
                       stb + aoff[mf] + s * 32);
#pragma unroll
            for (int np = 0; np < 2; ++np)
                ldm_x4(bfr[2 * np][0], bfr[2 * np][1],
                       bfr[2 * np + 1][0], bfr[2 * np + 1][1],
                       stb + boff[np] + s * 32);
#pragma unroll
            for (int mf = 0; mf < 4; ++mf)
#pragma unroll
                for (int nf = 0; nf < 4; ++nf)
                    mma_f16(acc[mf][nf][0], acc[mf][nf][1], acc[mf][nf][2], acc[mf][nf][3],
                            afr[mf][0], afr[mf][1], afr[mf][2], afr[mf][3],
                            bfr[nf][0], bfr[nf][1]);
        }
        ++st_c; if (st_c >= STAGES) st_c = 0;
    }
#undef CHUNK_OF
#undef LOAD_CHUNK

    // ---- epilogue: bias + activation; fp16 store for intermediates ----
#pragma unroll
    for (int mf = 0; mf < 4; ++mf) {
#pragma unroll
        for (int nf = 0; nf < 4; ++nf) {
            int row0 = rowA0 + warpM * 64 + mf * 16 + qr;
            int col0 = colB0 + warpN * 32 + nf * 8 + 2 * qc;
            float b0 = bias[col0];
            float b1 = bias[col0 + 1];
            float v0 = acc[mf][nf][0] + b0;
            float v1 = acc[mf][nf][1] + b1;
            float v2 = acc[mf][nf][2] + b0;
            float v3 = acc[mf][nf][3] + b1;
            if (act == ACT_TANH) {
                v0 = tanhf(v0); v1 = tanhf(v1); v2 = tanhf(v2); v3 = tanhf(v3);
            } else if (act == ACT_RELU) {
                v0 = fmaxf(v0, 0.f); v1 = fmaxf(v1, 0.f);
                v2 = fmaxf(v2, 0.f); v3 = fmaxf(v3, 0.f);
            }
            if (sizeof(OutT) == 2) {   // __half intermediate
                __half2* p0 = reinterpret_cast<__half2*>((__half*)C + (size_t)row0 * DIM + col0);
                __half2* p1 = reinterpret_cast<__half2*>((__half*)C + (size_t)(row0 + 8) * DIM + col0);
                *p0 = __floats2half2_rn(v0, v1);
                *p1 = __floats2half2_rn(v2, v3);
            } else {                    // float output (m / a)
                *reinterpret_cast<float2*>((float*)C + (size_t)row0 * DIM + col0)       = make_float2(v0, v1);
                *reinterpret_cast<float2*>((float*)C + (size_t)(row0 + 8) * DIM + col0) = make_float2(v2, v3);
            }
        }
    }
}

// ---------------- final elementwise + logdet --------------------------------
__global__ void final_kernel(const float* __restrict__ x, const float* __restrict__ m,
                             const float* __restrict__ a, float* __restrict__ out) {
    int b = blockIdx.x;
    int t = threadIdx.x;
    size_t base = (size_t)b * DIM;
    float s = 0.f;
#pragma unroll
    for (int i = 0; i < 4; ++i) {
        int c = t + i * 256;
        float av = a[base + c];
        float mv = m[base + c];
        float xv = x[base + c];
        out[base + c] = (xv - mv) * expf(-av);
        s += av;
    }
#pragma unroll
    for (int o = 16; o; o >>= 1) s += __shfl_down_sync(0xFFFFFFFFu, s, o);
    __shared__ float ws[8];
    if ((t & 31) == 0) ws[t >> 5] = s;
    __syncthreads();
    if (t < 8) {
        float v = ws[t];
#pragma unroll
        for (int o = 4; o; o >>= 1) v += __shfl_down_sync(0xFFu, v, o);
        if (t == 0) out[(size_t)BATCH * DIM + b] = -v;
    }
}

// ---------------- launcher ---------------------------------------------------
extern "C" void kernel_launch(void* const* d_in, const int* in_sizes, int n_in,
                              void* d_out, int out_size) {
    (void)in_sizes; (void)n_in; (void)out_size;
    const float* x      = (const float*)d_in[0];
    const float* s_w1   = (const float*)d_in[1];
    const float* s_b1   = (const float*)d_in[2];
    const float* s_w2   = (const float*)d_in[3];
    const float* s_b2   = (const float*)d_in[4];
    const float* s_w3   = (const float*)d_in[5];
    const float* s_b3   = (const float*)d_in[6];
    const float* t_w1   = (const float*)d_in[7];
    const float* t_b1   = (const float*)d_in[8];
    const float* t_w2   = (const float*)d_in[9];
    const float* t_b2   = (const float*)d_in[10];
    const float* t_w3   = (const float*)d_in[11];
    const float* t_b3   = (const float*)d_in[12];
    const float* mask_in  = (const float*)d_in[13];
    const float* mask_hid = (const float*)d_in[14];
    const float* mask_out = (const float*)d_in[15];
    float* out = (float*)d_out;

    __half *wm, *x16, *h1s, *h2s, *h1t, *h2t;
    float *mbuf, *abuf;
    cudaGetSymbolAddress((void**)&wm,   g_wm16);
    cudaGetSymbolAddress((void**)&x16,  g_x16);
    cudaGetSymbolAddress((void**)&h1s,  g_h1s);
    cudaGetSymbolAddress((void**)&h2s,  g_h2s);
    cudaGetSymbolAddress((void**)&h1t,  g_h1t);
    cudaGetSymbolAddress((void**)&h2t,  g_h2t);
    cudaGetSymbolAddress((void**)&mbuf, g_m);
    cudaGetSymbolAddress((void**)&abuf, g_a);

    const size_t WSZ = 1024u * 1024u;

    cudaFuncSetAttribute((const void*)gemm_dual_kernel<ACT_TANH, ACT_RELU, __half, false>,
                         cudaFuncAttributeMaxDynamicSharedMemorySize, GEMM_SMEM);
    cudaFuncSetAttribute((const void*)gemm_dual_kernel<ACT_TANH, ACT_RELU, __half, true>,
                         cudaFuncAttributeMaxDynamicSharedMemorySize, GEMM_SMEM);
    cudaFuncSetAttribute((const void*)gemm_dual_kernel<ACT_NONE, ACT_NONE, float, true>,
                         cudaFuncAttributeMaxDynamicSharedMemorySize, GEMM_SMEM);

    prep_weights6<<<1024, 256>>>(s_w1, s_w2, s_w3, t_w1, t_w2, t_w3,
                                 mask_in, mask_hid, mask_out, wm);
    prep_x_kernel<<<4096, 256>>>(x, x16);

    dim3 grid(8, BATCH / 128, 2);   // (8, 32, 2) = 512 CTAs, heavy-first
    // layer 1 (s: tanh, t: relu); mask_in has no wrap column
    gemm_dual_kernel<ACT_TANH, ACT_RELU, __half, false><<<grid, 256, GEMM_SMEM>>>(
        x16, x16, wm + 0 * WSZ, wm + 3 * WSZ, s_b1, t_b1, h1s, h1t);
    // layer 2 (s: tanh, t: relu); %1023 mask -> keep wrap chunk
    gemm_dual_kernel<ACT_TANH, ACT_RELU, __half, true><<<grid, 256, GEMM_SMEM>>>(
        h1s, h1t, wm + 1 * WSZ, wm + 4 * WSZ, s_b2, t_b2, h2s, h2t);
    // layer 3 (no activation), float outputs
    gemm_dual_kernel<ACT_NONE, ACT_NONE, float, true><<<grid, 256, GEMM_SMEM>>>(
        h2s, h2t, wm + 2 * WSZ, wm + 5 * WSZ, s_b3, t_b3, mbuf, abuf);

    final_kernel<<<BATCH, 256>>>(x, mbuf, abuf, out);
}

// round 9
// speedup vs baseline: 3.0813x; 1.2012x over previous
#include <cuda_runtime.h>
#include <cuda_fp16.h>
#include <cstdint>
#include <cstddef>

#define BATCH 4096
#define DIM   1024

// ---------------- scratch (static device memory) ----------------------------
__device__ __half g_wm16[6u * 1024u * 1024u];  // fp16 masked weights
__device__ __half g_x16 [BATCH * DIM];         // fp16 input copy
__device__ __half g_h1s [BATCH * DIM];
__device__ __half g_h2s [BATCH * DIM];
__device__ __half g_h1t [BATCH * DIM];
__device__ __half g_h2t [BATCH * DIM];
__device__ float  g_m   [BATCH * DIM];
__device__ float  g_a   [BATCH * DIM];

// ---------------- helpers ---------------------------------------------------
__device__ __forceinline__ uint32_t smem_u32(const void* p) {
    uint32_t a;
    asm("{ .reg .u64 t; cvta.to.shared.u64 t, %1; cvt.u32.u64 %0, t; }" : "=r"(a) : "l"(p));
    return a;
}

__device__ __forceinline__ void ldm_x4(uint32_t& r0, uint32_t& r1, uint32_t& r2, uint32_t& r3,
                                       uint32_t addr) {
    asm volatile("ldmatrix.sync.aligned.m8n8.x4.shared.b16 {%0,%1,%2,%3}, [%4];"
                 : "=r"(r0), "=r"(r1), "=r"(r2), "=r"(r3) : "r"(addr));
}

__device__ __forceinline__ void mma_f16(float& d0, float& d1, float& d2, float& d3,
                                        uint32_t a0, uint32_t a1, uint32_t a2, uint32_t a3,
                                        uint32_t b0, uint32_t b1) {
    asm("mma.sync.aligned.m16n8k16.row.col.f32.f16.f16.f32 "
        "{%0,%1,%2,%3},{%4,%5,%6,%7},{%8,%9},{%0,%1,%2,%3};\n"
        : "+f"(d0), "+f"(d1), "+f"(d2), "+f"(d3)
        : "r"(a0), "r"(a1), "r"(a2), "r"(a3), "r"(b0), "r"(b1));
}

#define CP_ASYNC16(dst, src) \
    asm volatile("cp.async.cg.shared.global [%0], [%1], 16;" :: "r"(dst), "l"(src) : "memory")
#define CP_COMMIT() asm volatile("cp.async.commit_group;" ::: "memory")
#define CP_WAIT1()  asm volatile("cp.async.wait_group 1;" ::: "memory")

// ---------------- prep kernels ----------------------------------------------
__global__ void prep_weights6(const float* __restrict__ sw1, const float* __restrict__ sw2,
                              const float* __restrict__ sw3, const float* __restrict__ tw1,
                              const float* __restrict__ tw2, const float* __restrict__ tw3,
                              const float* __restrict__ m1, const float* __restrict__ m2,
                              const float* __restrict__ m3, __half* __restrict__ dst) {
    const size_t WSZ = 1024u * 1024u;
    int i = blockIdx.x * blockDim.x + threadIdx.x;   // over 262144 float4
    float4 a1 = reinterpret_cast<const float4*>(m1)[i];
    float4 a2 = reinterpret_cast<const float4*>(m2)[i];
    float4 a3 = reinterpret_cast<const float4*>(m3)[i];
#define DO_W(wp, mk, slot) { \
        float4 wv = reinterpret_cast<const float4*>(wp)[i]; \
        __half2* d2 = reinterpret_cast<__half2*>(dst + (slot) * WSZ); \
        d2[2 * i]     = __floats2half2_rn(wv.x * mk.x, wv.y * mk.y); \
        d2[2 * i + 1] = __floats2half2_rn(wv.z * mk.z, wv.w * mk.w); }
    DO_W(sw1, a1, 0); DO_W(sw2, a2, 1); DO_W(sw3, a3, 2);
    DO_W(tw1, a1, 3); DO_W(tw2, a2, 4); DO_W(tw3, a3, 5);
#undef DO_W
}

__global__ void prep_x_kernel(const float* __restrict__ x, __half* __restrict__ dst) {
    int i = blockIdx.x * blockDim.x + threadIdx.x;
    float4 v = reinterpret_cast<const float4*>(x)[i];
    __half2* d2 = reinterpret_cast<__half2*>(dst);
    d2[2 * i]     = __floats2half2_rn(v.x, v.y);
    d2[2 * i + 1] = __floats2half2_rn(v.z, v.w);
}

// ---------------- fused dual-branch GEMM ------------------------------------
// Grid = (branch=2, M-blocks=32, cb-index=8). blockIdx.z is the SLOWEST
// launch dimension, so with cb = 7 - blockIdx.z ALL heavy (16-chunk) tiles
// launch before lighter ones -> LPT schedule, light tiles form the tail.
// fp16 in, fp32 acc. CTA tile 128x128, BK=64, 256 threads = 8 warps (2x4),
// warp tile 64x32. 3-stage cp.async pipeline (110 KB smem -> 2 CTAs/SM).
// Mask-aware K-skipping: column block cb only needs chunks [0, 2cb+2)
// (+ wrap chunk 15 for %1023 masks).
#define ACT_TANH 0
#define ACT_RELU 1
#define ACT_NONE 2

#define NCH 16                        // K / BK = 1024 / 64
#define STAGES 3
#define ROWB 144                      // bytes per padded smem row
#define STAGE_BYTES (256 * ROWB)      // 36864
#define B_SMEM_OFF  (128 * ROWB)      // 18432
#define GEMM_SMEM   (STAGES * STAGE_BYTES)   // 110592

template <int ACT0, int ACT1, typename OutT, bool ADDLAST>
__global__ __launch_bounds__(256, 2)
void gemm_dual_kernel(const __half* __restrict__ A0, const __half* __restrict__ A1,
                      const __half* __restrict__ W0, const __half* __restrict__ W1,
                      const float* __restrict__ bias0, const float* __restrict__ bias1,
                      OutT* __restrict__ C0, OutT* __restrict__ C1) {
    extern __shared__ __align__(16) char smc[];
    const uint32_t sbase = smem_u32(smc);

    const int z = blockIdx.x;                // branch select (fastest dim)
    const __half* A    = z ? A1 : A0;
    const __half* W    = z ? W1 : W0;
    const float*  bias = z ? bias1 : bias0;
    OutT*         C    = z ? C1 : C0;
    const int     act  = z ? ACT1 : ACT0;

    const int tid   = threadIdx.x;
    const int warp  = tid >> 5;
    const int lane  = tid & 31;
    const int warpM = warp >> 2;         // 0..1 -> 64 rows
    const int warpN = warp & 3;          // 0..3 -> 32 cols
    const int qr    = lane >> 2;         // 0..7
    const int qc    = lane & 3;          // 0..3

    const int rowA0 = blockIdx.y * 128;
    const int cb    = 7 - (int)blockIdx.z;   // heavy column blocks first
    const int colB0 = cb * 128;

    // ---- active K-chunk schedule ----
    const int Klim = min(NCH, cb * 2 + 2);
    const int NACT = (ADDLAST && Klim < NCH) ? Klim + 1 : Klim;
#define CHUNK_OF(j) (((j) < Klim) ? (j) : (NCH - 1))

    float acc[4][4][4];
#pragma unroll
    for (int mf = 0; mf < 4; ++mf)
#pragma unroll
        for (int nf = 0; nf < 4; ++nf)
#pragma unroll
            for (int r = 0; r < 4; ++r) acc[mf][nf][r] = 0.f;

    // ---- cp.async slot bases: 256 threads, 4 A slots + 4 B slots each ----
    const int r0 = tid >> 3;             // 0..31
    const int c  = tid & 7;              // 16B column within 128B row
    const __half* gA = A + (size_t)(rowA0 + r0) * DIM + c * 8;
    const __half* gB = W + (size_t)(colB0 + r0) * DIM + c * 8;
    const uint32_t sA = (uint32_t)(r0 * ROWB + c * 16);
    const uint32_t sB = (uint32_t)(B_SMEM_OFF + r0 * ROWB + c * 16);

#define LOAD_CHUNK(kt, st) do {                                              \
        uint32_t _b = sbase + (uint32_t)(st) * STAGE_BYTES;                  \
        const __half* _ga = gA + (kt) * 64;                                  \
        const __half* _gb = gB + (kt) * 64;                                  \
        _Pragma("unroll")                                                    \
        for (int _i = 0; _i < 4; ++_i) {                                     \
            CP_ASYNC16(_b + sA + _i * (32 * ROWB), _ga + _i * (32 * DIM));   \
            CP_ASYNC16(_b + sB + _i * (32 * ROWB), _gb + _i * (32 * DIM));   \
        }                                                                    \
    } while (0)

    // ---- ldmatrix per-thread base offsets ----
    uint32_t aoff[4], boff[2];
#pragma unroll
    for (int mf = 0; mf < 4; ++mf) {
        int arow = warpM * 64 + mf * 16 + (lane & 15);
        aoff[mf] = (uint32_t)(arow * ROWB + ((lane >> 4) & 1) * 16);
    }
#pragma unroll
    for (int np = 0; np < 2; ++np) {
        int brow = warpN * 32 + np * 16 + (lane & 7) + ((lane >> 4) & 1) * 8;
        boff[np] = (uint32_t)(B_SMEM_OFF + brow * ROWB + ((lane >> 3) & 1) * 16);
    }

    // Prologue: prefetch active chunks 0 and 1 (NACT >= 2 always)
    LOAD_CHUNK(CHUNK_OF(0), 0); CP_COMMIT();
    LOAD_CHUNK(CHUNK_OF(1), 1); CP_COMMIT();

    int st_c = 0;
    for (int j = 0; j < NACT; ++j) {
        CP_WAIT1();
        __syncthreads();

        if (j + 2 < NACT) {
            int st_n = st_c + 2; if (st_n >= STAGES) st_n -= STAGES;
            LOAD_CHUNK(CHUNK_OF(j + 2), st_n);
        }
        CP_COMMIT();

        const uint32_t stb = sbase + (uint32_t)st_c * STAGE_BYTES;
#pragma unroll
        for (int s = 0; s < 4; ++s) {        // k16 steps within the 64-chunk
            uint32_t afr[4][4];
            uint32_t bfr[4][2];
#pragma unroll
            for (int mf = 0; mf < 4; ++mf)
                ldm_x4(afr[mf][0], afr[mf][1], afr[mf][2], afr[mf][3],
                       stb + aoff[mf] + s * 32);
#pragma unroll
            for (int np = 0; np < 2; ++np)
                ldm_x4(bfr[2 * np][0], bfr[2 * np][1],
                       bfr[2 * np + 1][0], bfr[2 * np + 1][1],
                       stb + boff[np] + s * 32);
#pragma unroll
            for (int mf = 0; mf < 4; ++mf)
#pragma unroll
                for (int nf = 0; nf < 4; ++nf)
                    mma_f16(acc[mf][nf][0], acc[mf][nf][1], acc[mf][nf][2], acc[mf][nf][3],
                            afr[mf][0], afr[mf][1], afr[mf][2], afr[mf][3],
                            bfr[nf][0], bfr[nf][1]);
        }
        ++st_c; if (st_c >= STAGES) st_c = 0;
    }
#undef CHUNK_OF
#undef LOAD_CHUNK

    // ---- epilogue: bias + activation; fp16 store for intermediates ----
#pragma unroll
    for (int mf = 0; mf < 4; ++mf) {
#pragma unroll
        for (int nf = 0; nf < 4; ++nf) {
            int row0 = rowA0 + warpM * 64 + mf * 16 + qr;
            int col0 = colB0 + warpN * 32 + nf * 8 + 2 * qc;
            float b0 = bias[col0];
            float b1 = bias[col0 + 1];
            float v0 = acc[mf][nf][0] + b0;
            float v1 = acc[mf][nf][1] + b1;
            float v2 = acc[mf][nf][2] + b0;
            float v3 = acc[mf][nf][3] + b1;
            if (act == ACT_TANH) {
                v0 = tanhf(v0); v1 = tanhf(v1); v2 = tanhf(v2); v3 = tanhf(v3);
            } else if (act == ACT_RELU) {
                v0 = fmaxf(v0, 0.f); v1 = fmaxf(v1, 0.f);
                v2 = fmaxf(v2, 0.f); v3 = fmaxf(v3, 0.f);
            }
            if (sizeof(OutT) == 2) {   // __half intermediate
                __half2* p0 = reinterpret_cast<__half2*>((__half*)C + (size_t)row0 * DIM + col0);
                __half2* p1 = reinterpret_cast<__half2*>((__half*)C + (size_t)(row0 + 8) * DIM + col0);
                *p0 = __floats2half2_rn(v0, v1);
                *p1 = __floats2half2_rn(v2, v3);
            } else {                    // float output (m / a)
                *reinterpret_cast<float2*>((float*)C + (size_t)row0 * DIM + col0)       = make_float2(v0, v1);
                *reinterpret_cast<float2*>((float*)C + (size_t)(row0 + 8) * DIM + col0) = make_float2(v2, v3);
            }
        }
    }
}

// ---------------- final elementwise + logdet --------------------------------
__global__ void final_kernel(const float* __restrict__ x, const float* __restrict__ m,
                             const float* __restrict__ a, float* __restrict__ out) {
    int b = blockIdx.x;
    int t = threadIdx.x;
    size_t base = (size_t)b * DIM;
    float s = 0.f;
#pragma unroll
    for (int i = 0; i < 4; ++i) {
        int c = t + i * 256;
        float av = a[base + c];
        float mv = m[base + c];
        float xv = x[base + c];
        out[base + c] = (xv - mv) * expf(-av);
        s += av;
    }
#pragma unroll
    for (int o = 16; o; o >>= 1) s += __shfl_down_sync(0xFFFFFFFFu, s, o);
    __shared__ float ws[8];
    if ((t & 31) == 0) ws[t >> 5] = s;
    __syncthreads();
    if (t < 8) {
        float v = ws[t];
#pragma unroll
        for (int o = 4; o; o >>= 1) v += __shfl_down_sync(0xFFu, v, o);
        if (t == 0) out[(size_t)BATCH * DIM + b] = -v;
    }
}

// ---------------- launcher ---------------------------------------------------
extern "C" void kernel_launch(void* const* d_in, const int* in_sizes, int n_in,
                              void* d_out, int out_size) {
    (void)in_sizes; (void)n_in; (void)out_size;
    const float* x      = (const float*)d_in[0];
    const float* s_w1   = (const float*)d_in[1];
    const float* s_b1   = (const float*)d_in[2];
    const float* s_w2   = (const float*)d_in[3];
    const float* s_b2   = (const float*)d_in[4];
    const float* s_w3   = (const float*)d_in[5];
    const float* s_b3   = (const float*)d_in[6];
    const float* t_w1   = (const float*)d_in[7];
    const float* t_b1   = (const float*)d_in[8];
    const float* t_w2   = (const float*)d_in[9];
    const float* t_b2   = (const float*)d_in[10];
    const float* t_w3   = (const float*)d_in[11];
    const float* t_b3   = (const float*)d_in[12];
    const float* mask_in  = (const float*)d_in[13];
    const float* mask_hid = (const float*)d_in[14];
    const float* mask_out = (const float*)d_in[15];
    float* out = (float*)d_out;

    __half *wm, *x16, *h1s, *h2s, *h1t, *h2t;
    float *mbuf, *abuf;
    cudaGetSymbolAddress((void**)&wm,   g_wm16);
    cudaGetSymbolAddress((void**)&x16,  g_x16);
    cudaGetSymbolAddress((void**)&h1s,  g_h1s);
    cudaGetSymbolAddress((void**)&h2s,  g_h2s);
    cudaGetSymbolAddress((void**)&h1t,  g_h1t);
    cudaGetSymbolAddress((void**)&h2t,  g_h2t);
    cudaGetSymbolAddress((void**)&mbuf, g_m);
    cudaGetSymbolAddress((void**)&abuf, g_a);

    const size_t WSZ = 1024u * 1024u;

    cudaFuncSetAttribute((const void*)gemm_dual_kernel<ACT_TANH, ACT_RELU, __half, false>,
                         cudaFuncAttributeMaxDynamicSharedMemorySize, GEMM_SMEM);
    cudaFuncSetAttribute((const void*)gemm_dual_kernel<ACT_TANH, ACT_RELU, __half, true>,
                         cudaFuncAttributeMaxDynamicSharedMemorySize, GEMM_SMEM);
    cudaFuncSetAttribute((const void*)gemm_dual_kernel<ACT_NONE, ACT_NONE, float, true>,
                         cudaFuncAttributeMaxDynamicSharedMemorySize, GEMM_SMEM);

    prep_weights6<<<1024, 256>>>(s_w1, s_w2, s_w3, t_w1, t_w2, t_w3,
                                 mask_in, mask_hid, mask_out, wm);
    prep_x_kernel<<<4096, 256>>>(x, x16);

    // Grid (branch=2, M=32, cbi=8): z slowest -> all heavy tiles launch first.
    dim3 grid(2, BATCH / 128, 8);
    // layer 1 (s: tanh, t: relu); mask_in has no wrap column
    gemm_dual_kernel<ACT_TANH, ACT_RELU, __half, false><<<grid, 256, GEMM_SMEM>>>(
        x16, x16, wm + 0 * WSZ, wm + 3 * WSZ, s_b1, t_b1, h1s, h1t);
    // layer 2 (s: tanh, t: relu); %1023 mask -> keep wrap chunk
    gemm_dual_kernel<ACT_TANH, ACT_RELU, __half, true><<<grid, 256, GEMM_SMEM>>>(
        h1s, h1t, wm + 1 * WSZ, wm + 4 * WSZ, s_b2, t_b2, h2s, h2t);
    // layer 3 (no activation), float outputs
    gemm_dual_kernel<ACT_NONE, ACT_NONE, float, true><<<grid, 256, GEMM_SMEM>>>(
        h2s, h2t, wm + 2 * WSZ, wm + 5 * WSZ, s_b3, t_b3, mbuf, abuf);

    final_kernel<<<BATCH, 256>>>(x, mbuf, abuf, out);
}

// round 10
// speedup vs baseline: 3.2837x; 1.0657x over previous
#include <cuda_runtime.h>
#include <cuda_fp16.h>
#include <cstdint>
#include <cstddef>

#define BATCH 4096
#define DIM   1024

// ---------------- scratch (static device memory) ----------------------------
__device__ __half g_wm16[6u * 1024u * 1024u];  // fp16 masked weights
__device__ __half g_x16 [BATCH * DIM];         // fp16 input copy
__device__ __half g_h1s [BATCH * DIM];
__device__ __half g_h2s [BATCH * DIM];
__device__ __half g_h1t [BATCH * DIM];
__device__ __half g_h2t [BATCH * DIM];
__device__ float  g_m   [BATCH * DIM];
__device__ float  g_a   [BATCH * DIM];
__device__ unsigned g_done[2][2][32];          // [layer 0/1 done][branch][M-block]

// ---------------- helpers ---------------------------------------------------
__device__ __forceinline__ uint32_t smem_u32(const void* p) {
    uint32_t a;
    asm("{ .reg .u64 t; cvta.to.shared.u64 t, %1; cvt.u32.u64 %0, t; }" : "=r"(a) : "l"(p));
    return a;
}

__device__ __forceinline__ void ldm_x4(uint32_t& r0, uint32_t& r1, uint32_t& r2, uint32_t& r3,
                                       uint32_t addr) {
    asm volatile("ldmatrix.sync.aligned.m8n8.x4.shared.b16 {%0,%1,%2,%3}, [%4];"
                 : "=r"(r0), "=r"(r1), "=r"(r2), "=r"(r3) : "r"(addr));
}

__device__ __forceinline__ void mma_f16(float& d0, float& d1, float& d2, float& d3,
                                        uint32_t a0, uint32_t a1, uint32_t a2, uint32_t a3,
                                        uint32_t b0, uint32_t b1) {
    asm("mma.sync.aligned.m16n8k16.row.col.f32.f16.f16.f32 "
        "{%0,%1,%2,%3},{%4,%5,%6,%7},{%8,%9},{%0,%1,%2,%3};\n"
        : "+f"(d0), "+f"(d1), "+f"(d2), "+f"(d3)
        : "r"(a0), "r"(a1), "r"(a2), "r"(a3), "r"(b0), "r"(b1));
}

#define CP_ASYNC16(dst, src) \
    asm volatile("cp.async.cg.shared.global [%0], [%1], 16;" :: "r"(dst), "l"(src) : "memory")
#define CP_COMMIT() asm volatile("cp.async.commit_group;" ::: "memory")
#define CP_WAIT1()  asm volatile("cp.async.wait_group 1;" ::: "memory")

// ---------------- prep kernels ----------------------------------------------
__global__ void prep_weights6(const float* __restrict__ sw1, const float* __restrict__ sw2,
                              const float* __restrict__ sw3, const float* __restrict__ tw1,
                              const float* __restrict__ tw2, const float* __restrict__ tw3,
                              const float* __restrict__ m1, const float* __restrict__ m2,
                              const float* __restrict__ m3, __half* __restrict__ dst) {
    const size_t WSZ = 1024u * 1024u;
    int i = blockIdx.x * blockDim.x + threadIdx.x;   // over 262144 float4
    float4 a1 = reinterpret_cast<const float4*>(m1)[i];
    float4 a2 = reinterpret_cast<const float4*>(m2)[i];
    float4 a3 = reinterpret_cast<const float4*>(m3)[i];
#define DO_W(wp, mk, slot) { \
        float4 wv = reinterpret_cast<const float4*>(wp)[i]; \
        __half2* d2 = reinterpret_cast<__half2*>(dst + (slot) * WSZ); \
        d2[2 * i]     = __floats2half2_rn(wv.x * mk.x, wv.y * mk.y); \
        d2[2 * i + 1] = __floats2half2_rn(wv.z * mk.z, wv.w * mk.w); }
    DO_W(sw1, a1, 0); DO_W(sw2, a2, 1); DO_W(sw3, a3, 2);
    DO_W(tw1, a1, 3); DO_W(tw2, a2, 4); DO_W(tw3, a3, 5);
#undef DO_W
}

__global__ void prep_x_kernel(const float* __restrict__ x, __half* __restrict__ dst) {
    int i = blockIdx.x * blockDim.x + threadIdx.x;
    float4 v = reinterpret_cast<const float4*>(x)[i];
    __half2* d2 = reinterpret_cast<__half2*>(dst);
    d2[2 * i]     = __floats2half2_rn(v.x, v.y);
    d2[2 * i + 1] = __floats2half2_rn(v.z, v.w);
}

// ---------------- single-launch 3-layer dual-branch GEMM ---------------------
// Grid = (branch=2, M-blocks=32, zc=24); zc slowest. layer = zc>>3 (all layer-l
// blocks dispatch before layer-(l+1)), cb = 7-(zc&7) (LPT within layer).
// Inter-layer dependency is M-strip-local: a layer-l tile (b, y) waits on
// g_done[l-1][b][y] == 8 (spin + nanosleep), producers threadfence+atomicAdd.
// fp16 in, fp32 acc. CTA tile 128x128, BK=64, 256 threads, warp tile 64x32,
// 3-stage cp.async (110 KB smem -> 2 CTAs/SM). Mask-aware K-skipping as before.
#define ACT_TANH 0
#define ACT_RELU 1
#define ACT_NONE 2

#define NCH 16
#define STAGES 3
#define ROWB 144
#define STAGE_BYTES (256 * ROWB)
#define B_SMEM_OFF  (128 * ROWB)
#define GEMM_SMEM   (STAGES * STAGE_BYTES)   // 110592

__global__ __launch_bounds__(256, 2)
void gemm_made_kernel(const __half* __restrict__ x16,
                      __half* __restrict__ h1s, __half* __restrict__ h1t,
                      __half* __restrict__ h2s, __half* __restrict__ h2t,
                      const __half* __restrict__ wm,
                      const float* __restrict__ sb1, const float* __restrict__ sb2,
                      const float* __restrict__ sb3, const float* __restrict__ tb1,
                      const float* __restrict__ tb2, const float* __restrict__ tb3,
                      float* __restrict__ mbuf, float* __restrict__ abuf) {
    extern __shared__ __align__(16) char smc[];
    const uint32_t sbase = smem_u32(smc);
    const size_t WSZ = 1024u * 1024u;

    const int b     = blockIdx.x;            // branch
    const int y     = blockIdx.y;            // M-block
    const int zc    = blockIdx.z;
    const int layer = zc >> 3;                // 0,1,2
    const int cb    = 7 - (zc & 7);           // heavy column blocks first

    // ---- per-(layer,branch) operand selection ----
    const __half* A; const __half* W; const float* bias;
    void* C; int act; bool addlast;
    if (layer == 0) {
        A = x16;                W = wm + (b ? 3 : 0) * WSZ;
        bias = b ? tb1 : sb1;   C = b ? (void*)h1t : (void*)h1s;
        act = b ? ACT_RELU : ACT_TANH;  addlast = false;
    } else if (layer == 1) {
        A = b ? h1t : h1s;      W = wm + (b ? 4 : 1) * WSZ;
        bias = b ? tb2 : sb2;   C = b ? (void*)h2t : (void*)h2s;
        act = b ? ACT_RELU : ACT_TANH;  addlast = true;
    } else {
        A = b ? h2t : h2s;      W = wm + (b ? 5 : 2) * WSZ;
        bias = b ? tb3 : sb3;   C = b ? (void*)abuf : (void*)mbuf;
        act = ACT_NONE;                 addlast = true;
    }

    const int tid   = threadIdx.x;
    const int warp  = tid >> 5;
    const int lane  = tid & 31;
    const int warpM = warp >> 2;
    const int warpN = warp & 3;
    const int qr    = lane >> 2;
    const int qc    = lane & 3;

    const int rowA0 = y * 128;
    const int colB0 = cb * 128;

    // ---- wait for producing strip (layers 1,2) ----
    if (layer > 0) {
        if (tid == 0) {
            volatile unsigned* cnt = &g_done[layer - 1][b][y];
            while (*cnt < 8u) { __nanosleep(128); }
            __threadfence();
        }
        __syncthreads();
    }

    // ---- active K-chunk schedule ----
    const int Klim = min(NCH, cb * 2 + 2);
    const int NACT = (addlast && Klim < NCH) ? Klim + 1 : Klim;
#define CHUNK_OF(j) (((j) < Klim) ? (j) : (NCH - 1))

    float acc[4][4][4];
#pragma unroll
    for (int mf = 0; mf < 4; ++mf)
#pragma unroll
        for (int nf = 0; nf < 4; ++nf)
#pragma unroll
            for (int r = 0; r < 4; ++r) acc[mf][nf][r] = 0.f;

    // ---- cp.async slot bases ----
    const int r0 = tid >> 3;
    const int c  = tid & 7;
    const __half* gA = A + (size_t)(rowA0 + r0) * DIM + c * 8;
    const __half* gB = W + (size_t)(colB0 + r0) * DIM + c * 8;
    const uint32_t sA = (uint32_t)(r0 * ROWB + c * 16);
    const uint32_t sB = (uint32_t)(B_SMEM_OFF + r0 * ROWB + c * 16);

#define LOAD_CHUNK(kt, st) do {                                              \
        uint32_t _b = sbase + (uint32_t)(st) * STAGE_BYTES;                  \
        const __half* _ga = gA + (kt) * 64;                                  \
        const __half* _gb = gB + (kt) * 64;                                  \
        _Pragma("unroll")                                                    \
        for (int _i = 0; _i < 4; ++_i) {                                     \
            CP_ASYNC16(_b + sA + _i * (32 * ROWB), _ga + _i * (32 * DIM));   \
            CP_ASYNC16(_b + sB + _i * (32 * ROWB), _gb + _i * (32 * DIM));   \
        }                                                                    \
    } while (0)

    // ---- ldmatrix per-thread base offsets ----
    uint32_t aoff[4], boff[2];
#pragma unroll
    for (int mf = 0; mf < 4; ++mf) {
        int arow = warpM * 64 + mf * 16 + (lane & 15);
        aoff[mf] = (uint32_t)(arow * ROWB + ((lane >> 4) & 1) * 16);
    }
#pragma unroll
    for (int np = 0; np < 2; ++np) {
        int brow = warpN * 32 + np * 16 + (lane & 7) + ((lane >> 4) & 1) * 8;
        boff[np] = (uint32_t)(B_SMEM_OFF + brow * ROWB + ((lane >> 3) & 1) * 16);
    }

    // Prologue: prefetch active chunks 0 and 1 (NACT >= 2 always)
    LOAD_CHUNK(CHUNK_OF(0), 0); CP_COMMIT();
    LOAD_CHUNK(CHUNK_OF(1), 1); CP_COMMIT();

    int st_c = 0;
    for (int j = 0; j < NACT; ++j) {
        CP_WAIT1();
        __syncthreads();

        if (j + 2 < NACT) {
            int st_n = st_c + 2; if (st_n >= STAGES) st_n -= STAGES;
            LOAD_CHUNK(CHUNK_OF(j + 2), st_n);
        }
        CP_COMMIT();

        const uint32_t stb = sbase + (uint32_t)st_c * STAGE_BYTES;
#pragma unroll
        for (int s = 0; s < 4; ++s) {
            uint32_t afr[4][4];
            uint32_t bfr[4][2];
#pragma unroll
            for (int mf = 0; mf < 4; ++mf)
                ldm_x4(afr[mf][0], afr[mf][1], afr[mf][2], afr[mf][3],
                       stb + aoff[mf] + s * 32);
#pragma unroll
            for (int np = 0; np < 2; ++np)
                ldm_x4(bfr[2 * np][0], bfr[2 * np][1],
                       bfr[2 * np + 1][0], bfr[2 * np + 1][1],
                       stb + boff[np] + s * 32);
#pragma unroll
            for (int mf = 0; mf < 4; ++mf)
#pragma unroll
                for (int nf = 0; nf < 4; ++nf)
                    mma_f16(acc[mf][nf][0], acc[mf][nf][1], acc[mf][nf][2], acc[mf][nf][3],
                            afr[mf][0], afr[mf][1], afr[mf][2], afr[mf][3],
                            bfr[nf][0], bfr[nf][1]);
        }
        ++st_c; if (st_c >= STAGES) st_c = 0;
    }
#undef CHUNK_OF
#undef LOAD_CHUNK

    // ---- epilogue: bias + activation ----
#pragma unroll
    for (int mf = 0; mf < 4; ++mf) {
#pragma unroll
        for (int nf = 0; nf < 4; ++nf) {
            int row0 = rowA0 + warpM * 64 + mf * 16 + qr;
            int col0 = colB0 + warpN * 32 + nf * 8 + 2 * qc;
            float b0 = bias[col0];
            float b1 = bias[col0 + 1];
            float v0 = acc[mf][nf][0] + b0;
            float v1 = acc[mf][nf][1] + b1;
            float v2 = acc[mf][nf][2] + b0;
            float v3 = acc[mf][nf][3] + b1;
            if (act == ACT_TANH) {
                v0 = tanhf(v0); v1 = tanhf(v1); v2 = tanhf(v2); v3 = tanhf(v3);
            } else if (act == ACT_RELU) {
                v0 = fmaxf(v0, 0.f); v1 = fmaxf(v1, 0.f);
                v2 = fmaxf(v2, 0.f); v3 = fmaxf(v3, 0.f);
            }
            if (layer < 2) {   // __half intermediate
                __half2* p0 = reinterpret_cast<__half2*>((__half*)C + (size_t)row0 * DIM + col0);
                __half2* p1 = reinterpret_cast<__half2*>((__half*)C + (size_t)(row0 + 8) * DIM + col0);
                *p0 = __floats2half2_rn(v0, v1);
                *p1 = __floats2half2_rn(v2, v3);
            } else {            // float output (m / a)
                *reinterpret_cast<float2*>((float*)C + (size_t)row0 * DIM + col0)       = make_float2(v0, v1);
                *reinterpret_cast<float2*>((float*)C + (size_t)(row0 + 8) * DIM + col0) = make_float2(v2, v3);
            }
        }
    }

    // ---- signal completion (layers 0,1 feed a consumer) ----
    if (layer < 2) {
        __threadfence();          // all this thread's stores visible
        __syncthreads();          // all threads' stores done before signal
        if (tid == 0) atomicAdd(&g_done[layer][b][y], 1u);
    }
}

// ---------------- final elementwise + logdet --------------------------------
__global__ void final_kernel(const float* __restrict__ x, const float* __restrict__ m,
                             const float* __restrict__ a, float* __restrict__ out) {
    int b = blockIdx.x;
    int t = threadIdx.x;
    size_t base = (size_t)b * DIM;
    float s = 0.f;
#pragma unroll
    for (int i = 0; i < 4; ++i) {
        int c = t + i * 256;
        float av = a[base + c];
        float mv = m[base + c];
        float xv = x[base + c];
        out[base + c] = (xv - mv) * expf(-av);
        s += av;
    }
#pragma unroll
    for (int o = 16; o; o >>= 1) s += __shfl_down_sync(0xFFFFFFFFu, s, o);
    __shared__ float ws[8];
    if ((t & 31) == 0) ws[t >> 5] = s;
    __syncthreads();
    if (t < 8) {
        float v = ws[t];
#pragma unroll
        for (int o = 4; o; o >>= 1) v += __shfl_down_sync(0xFFu, v, o);
        if (t == 0) out[(size_t)BATCH * DIM + b] = -v;
    }
}

// ---------------- launcher ---------------------------------------------------
extern "C" void kernel_launch(void* const* d_in, const int* in_sizes, int n_in,
                              void* d_out, int out_size) {
    (void)in_sizes; (void)n_in; (void)out_size;
    const float* x      = (const float*)d_in[0];
    const float* s_w1   = (const float*)d_in[1];
    const float* s_b1   = (const float*)d_in[2];
    const float* s_w2   = (const float*)d_in[3];
    const float* s_b2   = (const float*)d_in[4];
    const float* s_w3   = (const float*)d_in[5];
    const float* s_b3   = (const float*)d_in[6];
    const float* t_w1   = (const float*)d_in[7];
    const float* t_b1   = (const float*)d_in[8];
    const float* t_w2   = (const float*)d_in[9];
    const float* t_b2   = (const float*)d_in[10];
    const float* t_w3   = (const float*)d_in[11];
    const float* t_b3   = (const float*)d_in[12];
    const float* mask_in  = (const float*)d_in[13];
    const float* mask_hid = (const float*)d_in[14];
    const float* mask_out = (const float*)d_in[15];
    float* out = (float*)d_out;

    __half *wm, *x16, *h1s, *h2s, *h1t, *h2t;
    float *mbuf, *abuf;
    void* doneptr;
    cudaGetSymbolAddress((void**)&wm,   g_wm16);
    cudaGetSymbolAddress((void**)&x16,  g_x16);
    cudaGetSymbolAddress((void**)&h1s,  g_h1s);
    cudaGetSymbolAddress((void**)&h2s,  g_h2s);
    cudaGetSymbolAddress((void**)&h1t,  g_h1t);
    cudaGetSymbolAddress((void**)&h2t,  g_h2t);
    cudaGetSymbolAddress((void**)&mbuf, g_m);
    cudaGetSymbolAddress((void**)&abuf, g_a);
    cudaGetSymbolAddress(&doneptr, g_done);

    cudaFuncSetAttribute((const void*)gemm_made_kernel,
                         cudaFuncAttributeMaxDynamicSharedMemorySize, GEMM_SMEM);

    // reset dependency counters (graph-capturable async memset, same stream)
    cudaMemsetAsync(doneptr, 0, sizeof(unsigned) * 2 * 2 * 32, 0);

    prep_weights6<<<1024, 256>>>(s_w1, s_w2, s_w3, t_w1, t_w2, t_w3,
                                 mask_in, mask_hid, mask_out, wm);
    prep_x_kernel<<<4096, 256>>>(x, x16);

    // One launch for all 3 layers x 2 branches; z slowest => layer-ordered, LPT.
    dim3 grid(2, BATCH / 128, 24);
    gemm_made_kernel<<<grid, 256, GEMM_SMEM>>>(
        x16, h1s, h1t, h2s, h2t, wm,
        s_b1, s_b2, s_b3, t_b1, t_b2, t_b3, mbuf, abuf);

    final_kernel<<<BATCH, 256>>>(x, mbuf, abuf, out);
}